// round 2
// baseline (speedup 1.0000x reference)
#include <cuda_runtime.h>

#define B_TOTAL   1024
#define T_STEPS   512
#define HID       64
#define NGATE     256
#define NB        8
#define NCTA      128
#define NTHREADS  256

typedef unsigned long long u64;

// Packed f32x2 FMA (Blackwell sm_103a): d = a*b + c elementwise on 2 floats.
__device__ __forceinline__ u64 ffma2(u64 a, u64 b, u64 c) {
    u64 d;
    asm("fma.rn.f32x2 %0, %1, %2, %3;" : "=l"(d) : "l"(a), "l"(b), "l"(c));
    return d;
}

__device__ __forceinline__ float hadd2(u64 v) {
    float lo, hi;
    asm("mov.b64 {%0, %1}, %2;" : "=f"(lo), "=f"(hi) : "l"(v));
    return lo + hi;
}

// HW tanh (MUFU.TANH): 1 MUFU op, ~2^-11 rel accuracy.
__device__ __forceinline__ float tanh_apx(float x) {
    float y;
    asm("tanh.approx.f32 %0, %1;" : "=f"(y) : "f"(x));
    return y;
}
// sigmoid(x) = 0.5*tanh(0.5x) + 0.5  -> 1 MUFU + 2 FMA
__device__ __forceinline__ float sig_apx(float x) {
    return fmaf(0.5f, tanh_apx(0.5f * x), 0.5f);
}

// Dynamic SMEM layout (bytes):
//   [0      .. 65536)  wih1q_s : ulonglong2 [16 kc][256 g]  (W_ih1, 4 floats per elem)
//   [65536  .. 81920)  x_s     : f32 [512 t][8 b]
//   [81920  .. 83968)  h0_s    : f32 [8 b][64 u]
//   [83968  .. 86016)  h1_s    : f32 [8 b][64 u]
//   [86016  .. 94208)  g0_s    : f32 [8 b][256 g]
//   [94208  ..102400)  g1_s    : f32 [8 b][256 g]
//   [102400 ..102656)  wfc_s   : f32 [64]
#define SMEM_BYTES 102656

__global__ void __launch_bounds__(NTHREADS, 1)
lstm2_kernel(const float* __restrict__ x,
             const float* __restrict__ W_ih0, const float* __restrict__ W_hh0,
             const float* __restrict__ b_ih0, const float* __restrict__ b_hh0,
             const float* __restrict__ W_ih1, const float* __restrict__ W_hh1,
             const float* __restrict__ b_ih1, const float* __restrict__ b_hh1,
             const float* __restrict__ W_fc,  const float* __restrict__ b_fc,
             float* __restrict__ out)
{
    extern __shared__ char smem_raw[];
    ulonglong2* wih1q_s = (ulonglong2*)(smem_raw);
    float* x_s     = (float*)(smem_raw + 65536);
    float* h0_s    = (float*)(smem_raw + 81920);
    float* h1_s    = (float*)(smem_raw + 83968);
    float* g0_s    = (float*)(smem_raw + 86016);
    float* g1_s    = (float*)(smem_raw + 94208);
    float* wfc_s   = (float*)(smem_raw + 102400);

    const int tid   = threadIdx.x;
    const int g     = tid;                 // gate row owned by this thread
    const int bbase = blockIdx.x * NB;

    // ---- per-thread recurrent weight rows, packed as f32x2 pairs in regs ----
    u64 whh0p[32], whh1p[32];
    {
        const ulonglong2* p0 = (const ulonglong2*)(W_hh0 + (size_t)g * HID);
        const ulonglong2* p1 = (const ulonglong2*)(W_hh1 + (size_t)g * HID);
#pragma unroll
        for (int j = 0; j < 16; j++) {
            ulonglong2 v0 = p0[j]; whh0p[2*j] = v0.x; whh0p[2*j+1] = v0.y;
            ulonglong2 v1 = p1[j]; whh1p[2*j] = v1.x; whh1p[2*j+1] = v1.y;
        }
    }
    const float b0v   = b_ih0[g] + b_hh0[g];
    const float b1v   = b_ih1[g] + b_hh1[g];
    const float wih0v = W_ih0[g];          // D == 1

    // ---- stage W_ih1 into SMEM: wih1q_s[kc*256 + g] = 4 consecutive k of row g ----
    for (int idx = tid; idx < NGATE * 16; idx += NTHREADS) {
        int gg = idx >> 4, kc = idx & 15;
        wih1q_s[kc * NGATE + gg] = ((const ulonglong2*)W_ih1)[gg * 16 + kc];
    }
    // ---- stage x tile, transposed to [t][b] ----
    for (int idx = tid; idx < NB * T_STEPS; idx += NTHREADS) {
        int b = idx >> 9, t = idx & (T_STEPS - 1);
        x_s[t * NB + b] = x[(size_t)(bbase + b) * T_STEPS + t];
    }
    if (tid < HID) wfc_s[tid] = W_fc[tid];
    for (int idx = tid; idx < NB * HID; idx += NTHREADS) { h0_s[idx] = 0.0f; h1_s[idx] = 0.0f; }
    __syncthreads();

    // activation-phase ownership: 512 (b,u) pairs -> 2 per thread
    const int bA = tid >> 6, uA = tid & 63;
    const int bB = bA + 4;
    float c0A = 0.0f, c0B = 0.0f, c1A = 0.0f, c1B = 0.0f;

    // ======== prologue: step 0, layer 0 (h0 == 0, so gates0 = b0 + wih0*x0) ========
#pragma unroll
    for (int b = 0; b < NB; b++)
        g0_s[b * NGATE + g] = fmaf(wih0v, x_s[0 * NB + b], b0v);
    __syncthreads();
    {   // act0(0)
        float xi = g0_s[bA * NGATE +       uA];
        float xf = g0_s[bA * NGATE +  64 + uA];
        float xg = g0_s[bA * NGATE + 128 + uA];
        float xo = g0_s[bA * NGATE + 192 + uA];
        float ii = sig_apx(xi), ff = sig_apx(xf), gv = tanh_apx(xg), oo = sig_apx(xo);
        c0A = ff * c0A + ii * gv;
        h0_s[bA * HID + uA] = oo * tanh_apx(c0A);

        xi = g0_s[bB * NGATE +       uA];
        xf = g0_s[bB * NGATE +  64 + uA];
        xg = g0_s[bB * NGATE + 128 + uA];
        xo = g0_s[bB * NGATE + 192 + uA];
        ii = sig_apx(xi); ff = sig_apx(xf); gv = tanh_apx(xg); oo = sig_apx(xo);
        c0B = ff * c0B + ii * gv;
        h0_s[bB * HID + uA] = oo * tanh_apx(c0B);
    }
    __syncthreads();

    // ======== main loop: phase A = {mv1(t), mv0(t+1)}, phase B = {act1(t), act0(t+1)} ========
    for (int t = 0; t < T_STEPS - 1; t++) {
        u64 acc[NB];

        // ---- mv0(t+1): gates0 = b0 + wih0*x[t+1] + W_hh0 . h0(t) ----
#pragma unroll
        for (int b = 0; b < NB; b++) acc[b] = 0ull;
#pragma unroll
        for (int kc = 0; kc < 16; kc++) {
            u64 w0 = whh0p[2*kc], w1 = whh0p[2*kc+1];
#pragma unroll
            for (int b = 0; b < NB; b++) {
                ulonglong2 h2 = *(const ulonglong2*)(h0_s + b * HID + kc * 4);
                acc[b] = ffma2(w0, h2.x, acc[b]);
                acc[b] = ffma2(w1, h2.y, acc[b]);
            }
        }
#pragma unroll
        for (int b = 0; b < NB; b++) {
            float a = hadd2(acc[b]);
            g0_s[b * NGATE + g] = fmaf(wih0v, x_s[(t + 1) * NB + b], a) + b0v;
        }

        // ---- mv1(t): gates1 = b1 + W_ih1 . h0(t) + W_hh1 . h1(t-1) ----
#pragma unroll
        for (int b = 0; b < NB; b++) acc[b] = 0ull;
#pragma unroll
        for (int kc = 0; kc < 16; kc++) {
            ulonglong2 w = wih1q_s[kc * NGATE + g];
#pragma unroll
            for (int b = 0; b < NB; b++) {
                ulonglong2 h2 = *(const ulonglong2*)(h0_s + b * HID + kc * 4);
                acc[b] = ffma2(w.x, h2.x, acc[b]);
                acc[b] = ffma2(w.y, h2.y, acc[b]);
            }
        }
#pragma unroll
        for (int kc = 0; kc < 16; kc++) {
            u64 w0 = whh1p[2*kc], w1 = whh1p[2*kc+1];
#pragma unroll
            for (int b = 0; b < NB; b++) {
                ulonglong2 h2 = *(const ulonglong2*)(h1_s + b * HID + kc * 4);
                acc[b] = ffma2(w0, h2.x, acc[b]);
                acc[b] = ffma2(w1, h2.y, acc[b]);
            }
        }
#pragma unroll
        for (int b = 0; b < NB; b++)
            g1_s[b * NGATE + g] = hadd2(acc[b]) + b1v;

        __syncthreads();   // A->B: gates ready; h reads done before overwrite

        // ---- act1(t) + act0(t+1): two independent MUFU chains, overlapped ----
        {
            float xiA1 = g1_s[bA * NGATE +       uA];
            float xfA1 = g1_s[bA * NGATE +  64 + uA];
            float xgA1 = g1_s[bA * NGATE + 128 + uA];
            float xoA1 = g1_s[bA * NGATE + 192 + uA];
            float xiA0 = g0_s[bA * NGATE +       uA];
            float xfA0 = g0_s[bA * NGATE +  64 + uA];
            float xgA0 = g0_s[bA * NGATE + 128 + uA];
            float xoA0 = g0_s[bA * NGATE + 192 + uA];

            float i1 = sig_apx(xiA1), f1 = sig_apx(xfA1), g1v = tanh_apx(xgA1), o1 = sig_apx(xoA1);
            float i0 = sig_apx(xiA0), f0 = sig_apx(xfA0), g0v = tanh_apx(xgA0), o0 = sig_apx(xoA0);
            c1A = f1 * c1A + i1 * g1v;
            c0A = f0 * c0A + i0 * g0v;
            h1_s[bA * HID + uA] = o1 * tanh_apx(c1A);
            h0_s[bA * HID + uA] = o0 * tanh_apx(c0A);

            float xiB1 = g1_s[bB * NGATE +       uA];
            float xfB1 = g1_s[bB * NGATE +  64 + uA];
            float xgB1 = g1_s[bB * NGATE + 128 + uA];
            float xoB1 = g1_s[bB * NGATE + 192 + uA];
            float xiB0 = g0_s[bB * NGATE +       uA];
            float xfB0 = g0_s[bB * NGATE +  64 + uA];
            float xgB0 = g0_s[bB * NGATE + 128 + uA];
            float xoB0 = g0_s[bB * NGATE + 192 + uA];

            i1 = sig_apx(xiB1); f1 = sig_apx(xfB1); g1v = tanh_apx(xgB1); o1 = sig_apx(xoB1);
            i0 = sig_apx(xiB0); f0 = sig_apx(xfB0); g0v = tanh_apx(xgB0); o0 = sig_apx(xoB0);
            c1B = f1 * c1B + i1 * g1v;
            c0B = f0 * c0B + i0 * g0v;
            h1_s[bB * HID + uA] = o1 * tanh_apx(c1B);
            h0_s[bB * HID + uA] = o0 * tanh_apx(c0B);
        }
        __syncthreads();   // B->A: h0/h1 visible
    }

    // ======== epilogue: mv1(511) + act1(511) ========
    {
        u64 acc[NB];
#pragma unroll
        for (int b = 0; b < NB; b++) acc[b] = 0ull;
#pragma unroll
        for (int kc = 0; kc < 16; kc++) {
            ulonglong2 w = wih1q_s[kc * NGATE + g];
#pragma unroll
            for (int b = 0; b < NB; b++) {
                ulonglong2 h2 = *(const ulonglong2*)(h0_s + b * HID + kc * 4);
                acc[b] = ffma2(w.x, h2.x, acc[b]);
                acc[b] = ffma2(w.y, h2.y, acc[b]);
            }
        }
#pragma unroll
        for (int kc = 0; kc < 16; kc++) {
            u64 w0 = whh1p[2*kc], w1 = whh1p[2*kc+1];
#pragma unroll
            for (int b = 0; b < NB; b++) {
                ulonglong2 h2 = *(const ulonglong2*)(h1_s + b * HID + kc * 4);
                acc[b] = ffma2(w0, h2.x, acc[b]);
                acc[b] = ffma2(w1, h2.y, acc[b]);
            }
        }
#pragma unroll
        for (int b = 0; b < NB; b++)
            g1_s[b * NGATE + g] = hadd2(acc[b]) + b1v;
        __syncthreads();

        float xi = g1_s[bA * NGATE +       uA];
        float xf = g1_s[bA * NGATE +  64 + uA];
        float xg = g1_s[bA * NGATE + 128 + uA];
        float xo = g1_s[bA * NGATE + 192 + uA];
        float ii = sig_apx(xi), ff = sig_apx(xf), gv = tanh_apx(xg), oo = sig_apx(xo);
        c1A = ff * c1A + ii * gv;
        h1_s[bA * HID + uA] = oo * tanh_apx(c1A);

        xi = g1_s[bB * NGATE +       uA];
        xf = g1_s[bB * NGATE +  64 + uA];
        xg = g1_s[bB * NGATE + 128 + uA];
        xo = g1_s[bB * NGATE + 192 + uA];
        ii = sig_apx(xi); ff = sig_apx(xf); gv = tanh_apx(xg); oo = sig_apx(xo);
        c1B = ff * c1B + ii * gv;
        h1_s[bB * HID + uA] = oo * tanh_apx(c1B);
    }
    __syncthreads();

    // ---- output: out[b] = h0f[b].Wfc + bfc ; out[1024+b] = h1f[b].Wfc + bfc ----
    if (tid < 2 * NB) {
        int b = tid & (NB - 1);
        const float* hp = (tid < NB) ? h0_s : h1_s;
        float s = b_fc[0];
#pragma unroll
        for (int u = 0; u < HID; u++) s = fmaf(hp[b * HID + u], wfc_s[u], s);
        out[(tid < NB ? 0 : B_TOTAL) + bbase + b] = s;
    }
}

extern "C" void kernel_launch(void* const* d_in, const int* in_sizes, int n_in,
                              void* d_out, int out_size) {
    const float* x     = (const float*)d_in[0];
    const float* W_ih0 = (const float*)d_in[1];
    const float* W_hh0 = (const float*)d_in[2];
    const float* b_ih0 = (const float*)d_in[3];
    const float* b_hh0 = (const float*)d_in[4];
    const float* W_ih1 = (const float*)d_in[5];
    const float* W_hh1 = (const float*)d_in[6];
    const float* b_ih1 = (const float*)d_in[7];
    const float* b_hh1 = (const float*)d_in[8];
    const float* W_fc  = (const float*)d_in[9];
    const float* b_fc  = (const float*)d_in[10];
    float* out = (float*)d_out;

    cudaFuncSetAttribute(lstm2_kernel,
                         cudaFuncAttributeMaxDynamicSharedMemorySize, SMEM_BYTES);
    lstm2_kernel<<<NCTA, NTHREADS, SMEM_BYTES>>>(
        x, W_ih0, W_hh0, b_ih0, b_hh0,
        W_ih1, W_hh1, b_ih1, b_hh1, W_fc, b_fc, out);
}

// round 3
// speedup vs baseline: 1.2210x; 1.2210x over previous
#include <cuda_runtime.h>

#define B_TOTAL   1024
#define T_STEPS   512
#define HID       64
#define NGATE     256
#define NB        8
#define NCTA      128
#define NTHREADS  512

typedef unsigned long long u64;

// Packed f32x2 FMA (Blackwell sm_103a).
__device__ __forceinline__ u64 ffma2(u64 a, u64 b, u64 c) {
    u64 d;
    asm("fma.rn.f32x2 %0, %1, %2, %3;" : "=l"(d) : "l"(a), "l"(b), "l"(c));
    return d;
}
__device__ __forceinline__ float hadd2(u64 v) {
    float lo, hi;
    asm("mov.b64 {%0, %1}, %2;" : "=f"(lo), "=f"(hi) : "l"(v));
    return lo + hi;
}
// HW tanh (MUFU.TANH), ~2^-11 rel accuracy.
__device__ __forceinline__ float tanh_apx(float x) {
    float y;
    asm("tanh.approx.f32 %0, %1;" : "=f"(y) : "f"(x));
    return y;
}
// sigmoid(x) = 0.5*tanh(0.5x) + 0.5
__device__ __forceinline__ float sig_apx(float x) {
    return fmaf(0.5f, tanh_apx(0.5f * x), 0.5f);
}

// Dynamic SMEM layout (bytes):
//   [0      .. 65536)  wih1q_s : ulonglong2 [16 q][256 g]   (W_ih1 quads, k-ascending)
//   [65536  .. 81920)  x_s     : f32 [512 t][8 b]
//   [81920  .. 98304)  g0p_s   : f32 [2 half][8 b][256 g]   (layer-0 gate partials)
//   [98304  ..114688)  g1p_s   : f32 [2 half][8 b][256 g]   (layer-1 gate partials)
//   [114688 ..116736)  h0_s    : f32 [8 b][64 u]
//   [116736 ..118784)  h1_s    : f32 [8 b][64 u]
//   [118784 ..119040)  wfc_s   : f32 [64]
#define SMEM_BYTES 119040

__global__ void __launch_bounds__(NTHREADS, 1)
lstm2_kernel(const float* __restrict__ x,
             const float* __restrict__ W_ih0, const float* __restrict__ W_hh0,
             const float* __restrict__ b_ih0, const float* __restrict__ b_hh0,
             const float* __restrict__ W_ih1, const float* __restrict__ W_hh1,
             const float* __restrict__ b_ih1, const float* __restrict__ b_hh1,
             const float* __restrict__ W_fc,  const float* __restrict__ b_fc,
             float* __restrict__ out)
{
    extern __shared__ char smem_raw[];
    ulonglong2* wih1q_s = (ulonglong2*)(smem_raw);
    float* x_s   = (float*)(smem_raw + 65536);
    float* g0p_s = (float*)(smem_raw + 81920);
    float* g1p_s = (float*)(smem_raw + 98304);
    float* h0_s  = (float*)(smem_raw + 114688);
    float* h1_s  = (float*)(smem_raw + 116736);
    float* wfc_s = (float*)(smem_raw + 118784);

    const int tid  = threadIdx.x;
    const int g    = tid & 255;        // gate row
    const int half = tid >> 8;         // k-half: 0 -> k[0..31], 1 -> k[32..63]
    const int kofs = half * 32;
    const int bbase = blockIdx.x * NB;

    // ---- per-thread recurrent weight half-rows in registers (32+32 regs) ----
    u64 whh0p[16], whh1p[16];
    {
        const ulonglong2* p0 = (const ulonglong2*)(W_hh0 + (size_t)g * HID + kofs);
        const ulonglong2* p1 = (const ulonglong2*)(W_hh1 + (size_t)g * HID + kofs);
#pragma unroll
        for (int j = 0; j < 8; j++) {
            ulonglong2 v0 = p0[j]; whh0p[2*j] = v0.x; whh0p[2*j+1] = v0.y;
            ulonglong2 v1 = p1[j]; whh1p[2*j] = v1.x; whh1p[2*j+1] = v1.y;
        }
    }
    const float b0v   = b_ih0[g] + b_hh0[g];   // applied by half 0 only
    const float b1v   = b_ih1[g] + b_hh1[g];
    const float wih0v = W_ih0[g];              // D == 1

    // ---- stage W_ih1 quads: wih1q_s[q*256 + g] = floats k[4q..4q+3] of row g ----
    for (int idx = tid; idx < NGATE * 16; idx += NTHREADS) {
        int gg = idx >> 4, q = idx & 15;
        wih1q_s[q * NGATE + gg] = ((const ulonglong2*)W_ih1)[gg * 16 + q];
    }
    // ---- stage x tile, transposed to [t][b] ----
    for (int idx = tid; idx < NB * T_STEPS; idx += NTHREADS) {
        int b = idx >> 9, t = idx & (T_STEPS - 1);
        x_s[t * NB + b] = x[(size_t)(bbase + b) * T_STEPS + t];
    }
    if (tid < HID) wfc_s[tid] = W_fc[tid];
    h0_s[tid] = 0.0f;   // NB*HID == 512 == NTHREADS
    h1_s[tid] = 0.0f;
    __syncthreads();

    // activation-phase ownership: one (b,u) cell per thread, per layer
    const int ub = tid & 63;
    const int bb = tid >> 6;
    float c0 = 0.0f, c1 = 0.0f;

    // ======== prologue: gates0(0) = b0 + wih0*x(0)  (h0(-1)=0) ========
#pragma unroll
    for (int b = 0; b < NB; b++)
        g0p_s[half * 2048 + b * NGATE + g] =
            (half == 0) ? fmaf(wih0v, x_s[b], b0v) : 0.0f;
    __syncthreads();
    {   // act0(0)
        float xi = g0p_s[bb * NGATE       + ub] + g0p_s[2048 + bb * NGATE       + ub];
        float xf = g0p_s[bb * NGATE +  64 + ub] + g0p_s[2048 + bb * NGATE +  64 + ub];
        float xg = g0p_s[bb * NGATE + 128 + ub] + g0p_s[2048 + bb * NGATE + 128 + ub];
        float xo = g0p_s[bb * NGATE + 192 + ub] + g0p_s[2048 + bb * NGATE + 192 + ub];
        float ii = sig_apx(xi), ff = sig_apx(xf), gv = tanh_apx(xg), oo = sig_apx(xo);
        c0 = ff * c0 + ii * gv;
        h0_s[bb * HID + ub] = oo * tanh_apx(c0);
    }
    __syncthreads();

    // ======== main loop: A = {mv0(t+1), mv1(t)} partials, B = {act1(t), act0(t+1)} ========
    for (int t = 0; t < T_STEPS - 1; t++) {
        u64 acc[NB];

        // ---- mv0(t+1) half-dot: W_hh0[g, kofs..] . h0(t)[b, kofs..] ----
#pragma unroll
        for (int b = 0; b < NB; b++) acc[b] = 0ull;
#pragma unroll
        for (int kc = 0; kc < 8; kc++) {
            u64 w0 = whh0p[2*kc], w1 = whh0p[2*kc+1];
#pragma unroll
            for (int b = 0; b < NB; b++) {
                ulonglong2 h2 = *(const ulonglong2*)(h0_s + b * HID + kofs + kc * 4);
                acc[b] = ffma2(w0, h2.x, acc[b]);
                acc[b] = ffma2(w1, h2.y, acc[b]);
            }
        }
#pragma unroll
        for (int b = 0; b < NB; b++) {
            float a = hadd2(acc[b]);
            if (half == 0) a = fmaf(wih0v, x_s[(t + 1) * NB + b], a) + b0v;
            g0p_s[half * 2048 + b * NGATE + g] = a;
        }

        // ---- mv1(t) half-dot: W_ih1 . h0(t) + W_hh1 . h1(t-1) ----
#pragma unroll
        for (int b = 0; b < NB; b++) acc[b] = 0ull;
#pragma unroll
        for (int kc = 0; kc < 8; kc++) {
            ulonglong2 w = wih1q_s[(half * 8 + kc) * NGATE + g];
#pragma unroll
            for (int b = 0; b < NB; b++) {
                ulonglong2 h2 = *(const ulonglong2*)(h0_s + b * HID + kofs + kc * 4);
                acc[b] = ffma2(w.x, h2.x, acc[b]);
                acc[b] = ffma2(w.y, h2.y, acc[b]);
            }
        }
#pragma unroll
        for (int kc = 0; kc < 8; kc++) {
            u64 w0 = whh1p[2*kc], w1 = whh1p[2*kc+1];
#pragma unroll
            for (int b = 0; b < NB; b++) {
                ulonglong2 h2 = *(const ulonglong2*)(h1_s + b * HID + kofs + kc * 4);
                acc[b] = ffma2(w0, h2.x, acc[b]);
                acc[b] = ffma2(w1, h2.y, acc[b]);
            }
        }
#pragma unroll
        for (int b = 0; b < NB; b++) {
            float a = hadd2(acc[b]);
            if (half == 0) a += b1v;
            g1p_s[half * 2048 + b * NGATE + g] = a;
        }

        __syncthreads();   // A->B: partials ready; h reads complete

        // ---- act1(t) then act0(t+1): combine halves inline ----
        {
            float xi1 = g1p_s[bb * NGATE       + ub] + g1p_s[2048 + bb * NGATE       + ub];
            float xf1 = g1p_s[bb * NGATE +  64 + ub] + g1p_s[2048 + bb * NGATE +  64 + ub];
            float xg1 = g1p_s[bb * NGATE + 128 + ub] + g1p_s[2048 + bb * NGATE + 128 + ub];
            float xo1 = g1p_s[bb * NGATE + 192 + ub] + g1p_s[2048 + bb * NGATE + 192 + ub];
            float xi0 = g0p_s[bb * NGATE       + ub] + g0p_s[2048 + bb * NGATE       + ub];
            float xf0 = g0p_s[bb * NGATE +  64 + ub] + g0p_s[2048 + bb * NGATE +  64 + ub];
            float xg0 = g0p_s[bb * NGATE + 128 + ub] + g0p_s[2048 + bb * NGATE + 128 + ub];
            float xo0 = g0p_s[bb * NGATE + 192 + ub] + g0p_s[2048 + bb * NGATE + 192 + ub];

            float i1 = sig_apx(xi1), f1 = sig_apx(xf1), g1v = tanh_apx(xg1), o1 = sig_apx(xo1);
            float i0 = sig_apx(xi0), f0 = sig_apx(xf0), g0v = tanh_apx(xg0), o0 = sig_apx(xo0);
            c1 = f1 * c1 + i1 * g1v;
            c0 = f0 * c0 + i0 * g0v;
            h1_s[bb * HID + ub] = o1 * tanh_apx(c1);
            h0_s[bb * HID + ub] = o0 * tanh_apx(c0);
        }
        __syncthreads();   // B->A: h0/h1 visible
    }

    // ======== epilogue: mv1(511) + act1(511) ========
    {
        u64 acc[NB];
#pragma unroll
        for (int b = 0; b < NB; b++) acc[b] = 0ull;
#pragma unroll
        for (int kc = 0; kc < 8; kc++) {
            ulonglong2 w = wih1q_s[(half * 8 + kc) * NGATE + g];
#pragma unroll
            for (int b = 0; b < NB; b++) {
                ulonglong2 h2 = *(const ulonglong2*)(h0_s + b * HID + kofs + kc * 4);
                acc[b] = ffma2(w.x, h2.x, acc[b]);
                acc[b] = ffma2(w.y, h2.y, acc[b]);
            }
        }
#pragma unroll
        for (int kc = 0; kc < 8; kc++) {
            u64 w0 = whh1p[2*kc], w1 = whh1p[2*kc+1];
#pragma unroll
            for (int b = 0; b < NB; b++) {
                ulonglong2 h2 = *(const ulonglong2*)(h1_s + b * HID + kofs + kc * 4);
                acc[b] = ffma2(w0, h2.x, acc[b]);
                acc[b] = ffma2(w1, h2.y, acc[b]);
            }
        }
#pragma unroll
        for (int b = 0; b < NB; b++) {
            float a = hadd2(acc[b]);
            if (half == 0) a += b1v;
            g1p_s[half * 2048 + b * NGATE + g] = a;
        }
        __syncthreads();

        float xi = g1p_s[bb * NGATE       + ub] + g1p_s[2048 + bb * NGATE       + ub];
        float xf = g1p_s[bb * NGATE +  64 + ub] + g1p_s[2048 + bb * NGATE +  64 + ub];
        float xg = g1p_s[bb * NGATE + 128 + ub] + g1p_s[2048 + bb * NGATE + 128 + ub];
        float xo = g1p_s[bb * NGATE + 192 + ub] + g1p_s[2048 + bb * NGATE + 192 + ub];
        float ii = sig_apx(xi), ff = sig_apx(xf), gv = tanh_apx(xg), oo = sig_apx(xo);
        c1 = ff * c1 + ii * gv;
        h1_s[bb * HID + ub] = oo * tanh_apx(c1);
    }
    __syncthreads();

    // ---- output: out[b] = h0f.Wfc + bfc ; out[1024+b] = h1f.Wfc + bfc ----
    if (tid < 2 * NB) {
        int b = tid & (NB - 1);
        const float* hp = (tid < NB) ? h0_s : h1_s;
        float s = b_fc[0];
#pragma unroll
        for (int u = 0; u < HID; u++) s = fmaf(hp[b * HID + u], wfc_s[u], s);
        out[(tid < NB ? 0 : B_TOTAL) + bbase + b] = s;
    }
}

extern "C" void kernel_launch(void* const* d_in, const int* in_sizes, int n_in,
                              void* d_out, int out_size) {
    const float* x     = (const float*)d_in[0];
    const float* W_ih0 = (const float*)d_in[1];
    const float* W_hh0 = (const float*)d_in[2];
    const float* b_ih0 = (const float*)d_in[3];
    const float* b_hh0 = (const float*)d_in[4];
    const float* W_ih1 = (const float*)d_in[5];
    const float* W_hh1 = (const float*)d_in[6];
    const float* b_ih1 = (const float*)d_in[7];
    const float* b_hh1 = (const float*)d_in[8];
    const float* W_fc  = (const float*)d_in[9];
    const float* b_fc  = (const float*)d_in[10];
    float* out = (float*)d_out;

    cudaFuncSetAttribute(lstm2_kernel,
                         cudaFuncAttributeMaxDynamicSharedMemorySize, SMEM_BYTES);
    lstm2_kernel<<<NCTA, NTHREADS, SMEM_BYTES>>>(
        x, W_ih0, W_hh0, b_ih0, b_hh0,
        W_ih1, W_hh1, b_ih1, b_hh1, W_fc, b_fc, out);
}

// round 5
// speedup vs baseline: 5.3214x; 4.3581x over previous
#include <cuda_runtime.h>

#define B_TOTAL   1024
#define T_STEPS   512
#define HID       64
#define NGATE     256
#define NB        8
#define NCTA      128
#define NTHREADS  512

typedef unsigned long long u64;

__device__ __forceinline__ u64 ffma2(u64 a, u64 b, u64 c) {
    u64 d;
    asm("fma.rn.f32x2 %0, %1, %2, %3;" : "=l"(d) : "l"(a), "l"(b), "l"(c));
    return d;
}
__device__ __forceinline__ float hadd2(u64 v) {
    float lo, hi;
    asm("mov.b64 {%0, %1}, %2;" : "=f"(lo), "=f"(hi) : "l"(v));
    return lo + hi;
}
__device__ __forceinline__ float tanh_apx(float x) {
    float y;
    asm("tanh.approx.f32 %0, %1;" : "=f"(y) : "f"(x));
    return y;
}
__device__ __forceinline__ float sig_apx(float x) {
    return fmaf(0.5f, tanh_apx(0.5f * x), 0.5f);
}

// SMEM layout (bytes). Weight quad layout: [8 kc][256 g][2 half] x 16B.
// h rows: stride 68 floats; half0 chunk at +0 (32 f), half1 chunk at +36 floats
// (= +144B -> +4 banks, disjoint from half0's 4 banks; 4-float pad at 32..35).
#define SM_WHH0   0
#define SM_WIH1   65536
#define SM_WHH1   131072
#define SM_G0     196608   /* f32 [8 b][256 g] */
#define SM_G1     204800
#define SM_H0     212992   /* f32 [8 b][68]    */
#define SM_H1     215168
#define SM_WFC    217344
#define SMEM_BYTES 217600

#define HSTRIDE   68

__global__ void __launch_bounds__(NTHREADS, 1)
lstm2_kernel(const float* __restrict__ x,
             const float* __restrict__ W_ih0, const float* __restrict__ W_hh0,
             const float* __restrict__ b_ih0, const float* __restrict__ b_hh0,
             const float* __restrict__ W_ih1, const float* __restrict__ W_hh1,
             const float* __restrict__ b_ih1, const float* __restrict__ b_hh1,
             const float* __restrict__ W_fc,  const float* __restrict__ b_fc,
             float* __restrict__ out)
{
    extern __shared__ char smem[];
    ulonglong2* whh0q_s = (ulonglong2*)(smem + SM_WHH0);
    ulonglong2* wih1q_s = (ulonglong2*)(smem + SM_WIH1);
    ulonglong2* whh1q_s = (ulonglong2*)(smem + SM_WHH1);
    float* g0_s  = (float*)(smem + SM_G0);
    float* g1_s  = (float*)(smem + SM_G1);
    float* h0_s  = (float*)(smem + SM_H0);
    float* h1_s  = (float*)(smem + SM_H1);
    float* wfc_s = (float*)(smem + SM_WFC);

    const int tid   = threadIdx.x;
    // lane-interleaved halves: lanes 0-15 half0, 16-31 half1, same 16 gate rows
    const int half  = (tid >> 4) & 1;
    const int g     = (tid & 15) | ((tid >> 5) << 4);   // 0..255
    const int g2h   = g * 2 + half;
    const int hofs  = half * 36;                        // float offset of k-half chunk
    const int bbase = blockIdx.x * NB;

    // ---- upload weights into SMEM quad layout: dest[(j&7)*512 + gg*2 + (j>>3)] ----
    for (int idx = tid; idx < 4096; idx += NTHREADS) {
        int j = idx & 15;
        int d = (j & 7) * 512 + (idx >> 4) * 2 + (j >> 3);
        whh0q_s[d] = ((const ulonglong2*)W_hh0)[idx];
        wih1q_s[d] = ((const ulonglong2*)W_ih1)[idx];
        whh1q_s[d] = ((const ulonglong2*)W_hh1)[idx];
    }
    if (tid < HID) wfc_s[tid] = W_fc[tid];
    for (int idx = tid; idx < NB * HSTRIDE; idx += NTHREADS) {
        h0_s[idx] = 0.0f; h1_s[idx] = 0.0f;
    }

    const float b0v = b_ih0[g] + b_hh0[g];
    const float b1v = b_ih1[g] + b_hh1[g];

    // act ownership: one (b,u) cell per thread per layer
    const int ub = tid & 63;
    const int bb = tid >> 6;
    const int hsto = bb * HSTRIDE + ub + ((ub >> 5) << 2);
    const float* xrow = x + (size_t)(bbase + bb) * T_STEPS;
    // per-act-thread input weights for its 4 gates (D == 1)
    const float wxi = W_ih0[ub];
    const float wxf = W_ih0[64 + ub];
    const float wxg = W_ih0[128 + ub];
    const float wxo = W_ih0[192 + ub];
    float c0 = 0.0f, c1 = 0.0f;
    __syncthreads();

    // ======== prologue: gates0(0) = b0 (+ x-term added by act threads) ========
    if (half == 0) {
#pragma unroll
        for (int b = 0; b < NB; b++)
            g0_s[b * NGATE + g] = b0v;
    }
    __syncthreads();
    {   // act0(0)
        float xv = __ldg(xrow);
        float xi = fmaf(wxi, xv, g0_s[bb * NGATE       + ub]);
        float xf = fmaf(wxf, xv, g0_s[bb * NGATE +  64 + ub]);
        float xg = fmaf(wxg, xv, g0_s[bb * NGATE + 128 + ub]);
        float xo = fmaf(wxo, xv, g0_s[bb * NGATE + 192 + ub]);
        float ii = sig_apx(xi), ff = sig_apx(xf), gv = tanh_apx(xg), oo = sig_apx(xo);
        c0 = ff * c0 + ii * gv;
        h0_s[hsto] = oo * tanh_apx(c0);
    }
    __syncthreads();

    // ======== main loop: A = {mv0(t+1), mv1(t)}, B = {act1(t), act0(t+1)} ========
    for (int t = 0; t < T_STEPS - 1; t++) {
        u64 a0[NB], a1[NB];
#pragma unroll
        for (int b = 0; b < NB; b++) { a0[b] = 0ull; a1[b] = 0ull; }

        // merged: whh0 . h0  and  wih1 . h0  (shared h0 loads)
#pragma unroll
        for (int kc = 0; kc < 8; kc++) {
            ulonglong2 wA = whh0q_s[kc * 512 + g2h];
            ulonglong2 wB = wih1q_s[kc * 512 + g2h];
#pragma unroll
            for (int b = 0; b < NB; b++) {
                ulonglong2 h2 = *(const ulonglong2*)(h0_s + b * HSTRIDE + hofs + kc * 4);
                a0[b] = ffma2(wA.x, h2.x, a0[b]);
                a0[b] = ffma2(wA.y, h2.y, a0[b]);
                a1[b] = ffma2(wB.x, h2.x, a1[b]);
                a1[b] = ffma2(wB.y, h2.y, a1[b]);
            }
        }
        // whh1 . h1
#pragma unroll
        for (int kc = 0; kc < 8; kc++) {
            ulonglong2 wC = whh1q_s[kc * 512 + g2h];
#pragma unroll
            for (int b = 0; b < NB; b++) {
                ulonglong2 h2 = *(const ulonglong2*)(h1_s + b * HSTRIDE + hofs + kc * 4);
                a1[b] = ffma2(wC.x, h2.x, a1[b]);
                a1[b] = ffma2(wC.y, h2.y, a1[b]);
            }
        }
        // cross-half reduction + gate stores (half0 lanes)
#pragma unroll
        for (int b = 0; b < NB; b++) {
            float s0 = hadd2(a0[b]);
            float s1 = hadd2(a1[b]);
            s0 += __shfl_xor_sync(0xffffffffu, s0, 16);
            s1 += __shfl_xor_sync(0xffffffffu, s1, 16);
            if (half == 0) {
                g0_s[b * NGATE + g] = s0 + b0v;
                g1_s[b * NGATE + g] = s1 + b1v;
            }
        }
        __syncthreads();   // A->B

        // act1(t), act0(t+1)
        {
            float xv  = __ldg(xrow + t + 1);
            float xi1 = g1_s[bb * NGATE       + ub];
            float xf1 = g1_s[bb * NGATE +  64 + ub];
            float xg1 = g1_s[bb * NGATE + 128 + ub];
            float xo1 = g1_s[bb * NGATE + 192 + ub];
            float xi0 = fmaf(wxi, xv, g0_s[bb * NGATE       + ub]);
            float xf0 = fmaf(wxf, xv, g0_s[bb * NGATE +  64 + ub]);
            float xg0 = fmaf(wxg, xv, g0_s[bb * NGATE + 128 + ub]);
            float xo0 = fmaf(wxo, xv, g0_s[bb * NGATE + 192 + ub]);

            float i1 = sig_apx(xi1), f1 = sig_apx(xf1), g1v = tanh_apx(xg1), o1 = sig_apx(xo1);
            float i0 = sig_apx(xi0), f0 = sig_apx(xf0), g0v = tanh_apx(xg0), o0 = sig_apx(xo0);
            c1 = f1 * c1 + i1 * g1v;
            c0 = f0 * c0 + i0 * g0v;
            h1_s[hsto] = o1 * tanh_apx(c1);
            h0_s[hsto] = o0 * tanh_apx(c0);
        }
        __syncthreads();   // B->A
    }

    // ======== epilogue: mv1(511) + act1(511) ========
    {
        u64 a1[NB];
#pragma unroll
        for (int b = 0; b < NB; b++) a1[b] = 0ull;
#pragma unroll
        for (int kc = 0; kc < 8; kc++) {
            ulonglong2 wB = wih1q_s[kc * 512 + g2h];
#pragma unroll
            for (int b = 0; b < NB; b++) {
                ulonglong2 h2 = *(const ulonglong2*)(h0_s + b * HSTRIDE + hofs + kc * 4);
                a1[b] = ffma2(wB.x, h2.x, a1[b]);
                a1[b] = ffma2(wB.y, h2.y, a1[b]);
            }
        }
#pragma unroll
        for (int kc = 0; kc < 8; kc++) {
            ulonglong2 wC = whh1q_s[kc * 512 + g2h];
#pragma unroll
            for (int b = 0; b < NB; b++) {
                ulonglong2 h2 = *(const ulonglong2*)(h1_s + b * HSTRIDE + hofs + kc * 4);
                a1[b] = ffma2(wC.x, h2.x, a1[b]);
                a1[b] = ffma2(wC.y, h2.y, a1[b]);
            }
        }
#pragma unroll
        for (int b = 0; b < NB; b++) {
            float s1 = hadd2(a1[b]);
            s1 += __shfl_xor_sync(0xffffffffu, s1, 16);
            if (half == 0) g1_s[b * NGATE + g] = s1 + b1v;
        }
        __syncthreads();

        float xi = g1_s[bb * NGATE       + ub];
        float xf = g1_s[bb * NGATE +  64 + ub];
        float xg = g1_s[bb * NGATE + 128 + ub];
        float xo = g1_s[bb * NGATE + 192 + ub];
        float ii = sig_apx(xi), ff = sig_apx(xf), gv = tanh_apx(xg), oo = sig_apx(xo);
        c1 = ff * c1 + ii * gv;
        h1_s[hsto] = oo * tanh_apx(c1);
    }
    __syncthreads();

    // ---- output: out[b] = h0f.Wfc + bfc ; out[1024+b] = h1f.Wfc + bfc ----
    if (tid < 2 * NB) {
        int b = tid & (NB - 1);
        const float* hp = (tid < NB) ? h0_s : h1_s;
        float s = b_fc[0];
#pragma unroll
        for (int u = 0; u < HID; u++)
            s = fmaf(hp[b * HSTRIDE + u + ((u >> 5) << 2)], wfc_s[u], s);
        out[(tid < NB ? 0 : B_TOTAL) + bbase + b] = s;
    }
}

extern "C" void kernel_launch(void* const* d_in, const int* in_sizes, int n_in,
                              void* d_out, int out_size) {
    const float* x     = (const float*)d_in[0];
    const float* W_ih0 = (const float*)d_in[1];
    const float* W_hh0 = (const float*)d_in[2];
    const float* b_ih0 = (const float*)d_in[3];
    const float* b_hh0 = (const float*)d_in[4];
    const float* W_ih1 = (const float*)d_in[5];
    const float* W_hh1 = (const float*)d_in[6];
    const float* b_ih1 = (const float*)d_in[7];
    const float* b_hh1 = (const float*)d_in[8];
    const float* W_fc  = (const float*)d_in[9];
    const float* b_fc  = (const float*)d_in[10];
    float* out = (float*)d_out;

    cudaFuncSetAttribute(lstm2_kernel,
                         cudaFuncAttributeMaxDynamicSharedMemorySize, SMEM_BYTES);
    lstm2_kernel<<<NCTA, NTHREADS, SMEM_BYTES>>>(
        x, W_ih0, W_hh0, b_ih0, b_hh0,
        W_ih1, W_hh1, b_ih1, b_hh1, W_fc, b_fc, out);
}

// round 6
// speedup vs baseline: 6.8022x; 1.2783x over previous
#include <cuda_runtime.h>

#define B_TOTAL   1024
#define T_STEPS   512
#define NGATE     256
#define NB        8
#define NCTA      128
#define NTHREADS  384
#define HSTRIDE   68

typedef unsigned long long u64;

__device__ __forceinline__ u64 ffma2(u64 a, u64 b, u64 c) {
    u64 d;
    asm("fma.rn.f32x2 %0, %1, %2, %3;" : "=l"(d) : "l"(a), "l"(b), "l"(c));
    return d;
}
__device__ __forceinline__ float hadd2(u64 v) {
    float lo, hi;
    asm("mov.b64 {%0, %1}, %2;" : "=f"(lo), "=f"(hi) : "l"(v));
    return lo + hi;
}
__device__ __forceinline__ float tanh_apx(float x) {
    float y;
    asm("tanh.approx.f32 %0, %1;" : "=f"(y) : "f"(x));
    return y;
}
__device__ __forceinline__ float sig_apx(float x) {
    return fmaf(0.5f, tanh_apx(0.5f * x), 0.5f);
}

// SMEM (bytes):
//  wq   [0, 196608): quads. A=whh0 [0,4096), B=wih1 [4096,8192), C=whh1 [8192,12288)
//       A/B sublayout: [rowhi][kc][ (row&127)*2 + half ]  (2048-quad blocks)
//       C   sublayout: [row>>6][kc][ (row&63)*2 + half ]  (1024-quad blocks)
//  g0   [196608): f32 [8 b][256 g]
//  g1a  [204800): f32 [8 b][256 g]   (alpha partial, includes b1)
//  g1b  [212992): f32 [8 b][256 g]   (beta partial)
//  h0   [221184): f32 [8 b][68]      half0 @ +0, half1 @ +36 floats
//  h1   [223360)
//  wfc  [225536): f32 [64]
#define SM_W      0
#define SM_G0     196608
#define SM_G1A    204800
#define SM_G1B    212992
#define SM_H0     221184
#define SM_H1     223360
#define SM_WFC    225536
#define SMEM_BYTES 225792

__global__ void __launch_bounds__(NTHREADS, 1)
lstm2_kernel(const float* __restrict__ x,
             const float* __restrict__ W_ih0, const float* __restrict__ W_hh0,
             const float* __restrict__ b_ih0, const float* __restrict__ b_hh0,
             const float* __restrict__ W_ih1, const float* __restrict__ W_hh1,
             const float* __restrict__ b_ih1, const float* __restrict__ b_hh1,
             const float* __restrict__ W_fc,  const float* __restrict__ b_fc,
             float* __restrict__ out)
{
    extern __shared__ char smem[];
    ulonglong2* wq = (ulonglong2*)(smem + SM_W);
    float* g0_s  = (float*)(smem + SM_G0);
    float* g1a_s = (float*)(smem + SM_G1A);
    float* g1b_s = (float*)(smem + SM_G1B);
    float* h0_s  = (float*)(smem + SM_H0);
    float* h1_s  = (float*)(smem + SM_H1);
    float* wfc_s = (float*)(smem + SM_WFC);

    const int tid   = threadIdx.x;
    const int bbase = blockIdx.x * NB;
    const int lane  = tid & 31;
    const int half  = lane >> 4;        // k-half within warp
    const int hofs  = half * 36;        // h chunk float offset
    const int wid   = tid >> 5;

    // ---- upload weights into role-specific quad layouts ----
    for (int idx = tid; idx < 4096; idx += NTHREADS) {
        int row = idx >> 4, q = idx & 15;
        int hh = q >> 3, kc = q & 7;
        int dA = (row >> 7) * 2048 + kc * 256 + (row & 127) * 2 + hh;
        wq[dA]        = ((const ulonglong2*)W_hh0)[idx];
        wq[4096 + dA] = ((const ulonglong2*)W_ih1)[idx];
        int dC = 8192 + (row >> 6) * 1024 + kc * 128 + (row & 63) * 2 + hh;
        wq[dC] = ((const ulonglong2*)W_hh1)[idx];
    }
    if (tid < 64) wfc_s[tid] = W_fc[tid];
    for (int i = tid; i < NB * HSTRIDE; i += NTHREADS) { h0_s[i] = 0.0f; h1_s[i] = 0.0f; }

    // ---- role constants ----
    const bool isA = (tid < 256);
    // alpha: warps 0-7, slot sl in [0,128), rows {sl, sl+128}
    const int sl   = (wid & 7) * 16 + (lane & 15);
    const int sl2h = sl * 2 + half;
    const int myrow = sl + half * 128;          // row this lane stores
    // beta: warps 8-11, slot sb in [0,64), rows {sb, sb+64, sb+128, sb+192}
    const int sb   = (wid - 8) * 16 + (lane & 15);
    const int sb2h = sb * 2 + half;
    const int rX   = sb + 64 * (half * 2);      // beta store rows
    const int rY   = rX + 64;

    float b0v = 0.0f, b1v = 0.0f;
    if (isA) {
        b0v = b_ih0[myrow] + b_hh0[myrow];
        b1v = b_ih1[myrow] + b_hh1[myrow];
    }

    // ---- act ownership: cell1 = tid; cell2 = 384 + tid (tid<128) ----
    const int u   = tid & 63;
    const int b1c = tid >> 6;                   // 0..5
    const int b2c = b1c + 6;                    // 6..7 for tid<128
    const int gi1 = b1c * NGATE + u;
    const int gi2 = b2c * NGATE + u;
    const int pad = (u >> 5) << 2;
    const int hsto1 = b1c * HSTRIDE + u + pad;
    const int hsto2 = b2c * HSTRIDE + u + pad;
    const float* xrow1 = x + (size_t)(bbase + b1c) * T_STEPS;
    const float* xrow2 = x + (size_t)(bbase + b2c) * T_STEPS;
    const float wxi = W_ih0[u];
    const float wxf = W_ih0[64 + u];
    const float wxg = W_ih0[128 + u];
    const float wxo = W_ih0[192 + u];
    float c0_1 = 0.0f, c1_1 = 0.0f, c0_2 = 0.0f, c1_2 = 0.0f;

    // ---- prologue: g0(0) = b0 ----
    if (isA) {
#pragma unroll
        for (int b = 0; b < NB; b++) g0_s[b * NGATE + myrow] = b0v;
    }
    __syncthreads();
    {   // act0(0)
        float xv = __ldg(xrow1);
        float q0 = fmaf(wxi, xv, g0_s[gi1]);
        float q1 = fmaf(wxf, xv, g0_s[gi1 + 64]);
        float q2 = fmaf(wxg, xv, g0_s[gi1 + 128]);
        float q3 = fmaf(wxo, xv, g0_s[gi1 + 192]);
        float i0 = sig_apx(q0), f0 = sig_apx(q1), g0v = tanh_apx(q2), o0 = sig_apx(q3);
        c0_1 = f0 * c0_1 + i0 * g0v;
        h0_s[hsto1] = o0 * tanh_apx(c0_1);
        if (tid < 128) {
            float xw = __ldg(xrow2);
            float r0 = fmaf(wxi, xw, g0_s[gi2]);
            float r1 = fmaf(wxf, xw, g0_s[gi2 + 64]);
            float r2 = fmaf(wxg, xw, g0_s[gi2 + 128]);
            float r3 = fmaf(wxo, xw, g0_s[gi2 + 192]);
            float i2 = sig_apx(r0), f2 = sig_apx(r1), g2v = tanh_apx(r2), o2 = sig_apx(r3);
            c0_2 = f2 * c0_2 + i2 * g2v;
            h0_s[hsto2] = o2 * tanh_apx(c0_2);
        }
    }
    __syncthreads();

    // ======== main loop ========
    for (int t = 0; t < T_STEPS - 1; t++) {
        if (isA) {
            u64 aA0[NB], aA1[NB], aB0[NB], aB1[NB];
#pragma unroll
            for (int b = 0; b < NB; b++) { aA0[b]=0ull; aA1[b]=0ull; aB0[b]=0ull; aB1[b]=0ull; }
#pragma unroll
            for (int kc = 0; kc < 8; kc++) {
                ulonglong2 wa0 = wq[       kc * 256 + sl2h];
                ulonglong2 wa1 = wq[2048 + kc * 256 + sl2h];
                ulonglong2 wb0 = wq[4096 + kc * 256 + sl2h];
                ulonglong2 wb1 = wq[6144 + kc * 256 + sl2h];
#pragma unroll
                for (int b = 0; b < NB; b++) {
                    ulonglong2 h2 = *(const ulonglong2*)(h0_s + b * HSTRIDE + hofs + kc * 4);
                    aA0[b] = ffma2(wa0.x, h2.x, aA0[b]); aA0[b] = ffma2(wa0.y, h2.y, aA0[b]);
                    aA1[b] = ffma2(wa1.x, h2.x, aA1[b]); aA1[b] = ffma2(wa1.y, h2.y, aA1[b]);
                    aB0[b] = ffma2(wb0.x, h2.x, aB0[b]); aB0[b] = ffma2(wb0.y, h2.y, aB0[b]);
                    aB1[b] = ffma2(wb1.x, h2.x, aB1[b]); aB1[b] = ffma2(wb1.y, h2.y, aB1[b]);
                }
            }
#pragma unroll
            for (int b = 0; b < NB; b++) {
                float sA0 = hadd2(aA0[b]); sA0 += __shfl_xor_sync(0xffffffffu, sA0, 16);
                float sA1 = hadd2(aA1[b]); sA1 += __shfl_xor_sync(0xffffffffu, sA1, 16);
                float sB0 = hadd2(aB0[b]); sB0 += __shfl_xor_sync(0xffffffffu, sB0, 16);
                float sB1 = hadd2(aB1[b]); sB1 += __shfl_xor_sync(0xffffffffu, sB1, 16);
                g0_s [b * NGATE + myrow] = (half ? sA1 : sA0) + b0v;
                g1a_s[b * NGATE + myrow] = (half ? sB1 : sB0) + b1v;
            }
        } else {
            u64 aC0[NB], aC1[NB], aC2[NB], aC3[NB];
#pragma unroll
            for (int b = 0; b < NB; b++) { aC0[b]=0ull; aC1[b]=0ull; aC2[b]=0ull; aC3[b]=0ull; }
#pragma unroll
            for (int kc = 0; kc < 8; kc++) {
                ulonglong2 wc0 = wq[8192        + kc * 128 + sb2h];
                ulonglong2 wc1 = wq[8192 + 1024 + kc * 128 + sb2h];
                ulonglong2 wc2 = wq[8192 + 2048 + kc * 128 + sb2h];
                ulonglong2 wc3 = wq[8192 + 3072 + kc * 128 + sb2h];
#pragma unroll
                for (int b = 0; b < NB; b++) {
                    ulonglong2 h2 = *(const ulonglong2*)(h1_s + b * HSTRIDE + hofs + kc * 4);
                    aC0[b] = ffma2(wc0.x, h2.x, aC0[b]); aC0[b] = ffma2(wc0.y, h2.y, aC0[b]);
                    aC1[b] = ffma2(wc1.x, h2.x, aC1[b]); aC1[b] = ffma2(wc1.y, h2.y, aC1[b]);
                    aC2[b] = ffma2(wc2.x, h2.x, aC2[b]); aC2[b] = ffma2(wc2.y, h2.y, aC2[b]);
                    aC3[b] = ffma2(wc3.x, h2.x, aC3[b]); aC3[b] = ffma2(wc3.y, h2.y, aC3[b]);
                }
            }
#pragma unroll
            for (int b = 0; b < NB; b++) {
                float s0 = hadd2(aC0[b]); s0 += __shfl_xor_sync(0xffffffffu, s0, 16);
                float s1 = hadd2(aC1[b]); s1 += __shfl_xor_sync(0xffffffffu, s1, 16);
                float s2 = hadd2(aC2[b]); s2 += __shfl_xor_sync(0xffffffffu, s2, 16);
                float s3 = hadd2(aC3[b]); s3 += __shfl_xor_sync(0xffffffffu, s3, 16);
                g1b_s[b * NGATE + rX] = half ? s2 : s0;
                g1b_s[b * NGATE + rY] = half ? s3 : s1;
            }
        }
        __syncthreads();   // A -> B

        // ---- act1(t), act0(t+1) ----
        {
            float xv = __ldg(xrow1 + t + 1);
            float p0 = g1a_s[gi1]       + g1b_s[gi1];
            float p1 = g1a_s[gi1 + 64]  + g1b_s[gi1 + 64];
            float p2 = g1a_s[gi1 + 128] + g1b_s[gi1 + 128];
            float p3 = g1a_s[gi1 + 192] + g1b_s[gi1 + 192];
            float q0 = fmaf(wxi, xv, g0_s[gi1]);
            float q1 = fmaf(wxf, xv, g0_s[gi1 + 64]);
            float q2 = fmaf(wxg, xv, g0_s[gi1 + 128]);
            float q3 = fmaf(wxo, xv, g0_s[gi1 + 192]);
            float i1 = sig_apx(p0), f1 = sig_apx(p1), g1v = tanh_apx(p2), o1 = sig_apx(p3);
            float i0 = sig_apx(q0), f0 = sig_apx(q1), g0v = tanh_apx(q2), o0 = sig_apx(q3);
            c1_1 = f1 * c1_1 + i1 * g1v;
            c0_1 = f0 * c0_1 + i0 * g0v;
            h1_s[hsto1] = o1 * tanh_apx(c1_1);
            h0_s[hsto1] = o0 * tanh_apx(c0_1);

            if (tid < 128) {
                float xw = __ldg(xrow2 + t + 1);
                float e0 = g1a_s[gi2]       + g1b_s[gi2];
                float e1 = g1a_s[gi2 + 64]  + g1b_s[gi2 + 64];
                float e2 = g1a_s[gi2 + 128] + g1b_s[gi2 + 128];
                float e3 = g1a_s[gi2 + 192] + g1b_s[gi2 + 192];
                float r0 = fmaf(wxi, xw, g0_s[gi2]);
                float r1 = fmaf(wxf, xw, g0_s[gi2 + 64]);
                float r2 = fmaf(wxg, xw, g0_s[gi2 + 128]);
                float r3 = fmaf(wxo, xw, g0_s[gi2 + 192]);
                float i3 = sig_apx(e0), f3 = sig_apx(e1), g3v = tanh_apx(e2), o3 = sig_apx(e3);
                float i2 = sig_apx(r0), f2 = sig_apx(r1), g2v = tanh_apx(r2), o2 = sig_apx(r3);
                c1_2 = f3 * c1_2 + i3 * g3v;
                c0_2 = f2 * c0_2 + i2 * g2v;
                h1_s[hsto2] = o3 * tanh_apx(c1_2);
                h0_s[hsto2] = o2 * tanh_apx(c0_2);
            }
        }
        __syncthreads();   // B -> A
    }

    // ======== epilogue: mv1(511) + act1(511) ========
    if (isA) {
        u64 aB0[NB], aB1[NB];
#pragma unroll
        for (int b = 0; b < NB; b++) { aB0[b] = 0ull; aB1[b] = 0ull; }
#pragma unroll
        for (int kc = 0; kc < 8; kc++) {
            ulonglong2 wb0 = wq[4096 + kc * 256 + sl2h];
            ulonglong2 wb1 = wq[6144 + kc * 256 + sl2h];
#pragma unroll
            for (int b = 0; b < NB; b++) {
                ulonglong2 h2 = *(const ulonglong2*)(h0_s + b * HSTRIDE + hofs + kc * 4);
                aB0[b] = ffma2(wb0.x, h2.x, aB0[b]); aB0[b] = ffma2(wb0.y, h2.y, aB0[b]);
                aB1[b] = ffma2(wb1.x, h2.x, aB1[b]); aB1[b] = ffma2(wb1.y, h2.y, aB1[b]);
            }
        }
#pragma unroll
        for (int b = 0; b < NB; b++) {
            float sB0 = hadd2(aB0[b]); sB0 += __shfl_xor_sync(0xffffffffu, sB0, 16);
            float sB1 = hadd2(aB1[b]); sB1 += __shfl_xor_sync(0xffffffffu, sB1, 16);
            g1a_s[b * NGATE + myrow] = (half ? sB1 : sB0) + b1v;
        }
    } else {
        u64 aC0[NB], aC1[NB], aC2[NB], aC3[NB];
#pragma unroll
        for (int b = 0; b < NB; b++) { aC0[b]=0ull; aC1[b]=0ull; aC2[b]=0ull; aC3[b]=0ull; }
#pragma unroll
        for (int kc = 0; kc < 8; kc++) {
            ulonglong2 wc0 = wq[8192        + kc * 128 + sb2h];
            ulonglong2 wc1 = wq[8192 + 1024 + kc * 128 + sb2h];
            ulonglong2 wc2 = wq[8192 + 2048 + kc * 128 + sb2h];
            ulonglong2 wc3 = wq[8192 + 3072 + kc * 128 + sb2h];
#pragma unroll
            for (int b = 0; b < NB; b++) {
                ulonglong2 h2 = *(const ulonglong2*)(h1_s + b * HSTRIDE + hofs + kc * 4);
                aC0[b] = ffma2(wc0.x, h2.x, aC0[b]); aC0[b] = ffma2(wc0.y, h2.y, aC0[b]);
                aC1[b] = ffma2(wc1.x, h2.x, aC1[b]); aC1[b] = ffma2(wc1.y, h2.y, aC1[b]);
                aC2[b] = ffma2(wc2.x, h2.x, aC2[b]); aC2[b] = ffma2(wc2.y, h2.y, aC2[b]);
                aC3[b] = ffma2(wc3.x, h2.x, aC3[b]); aC3[b] = ffma2(wc3.y, h2.y, aC3[b]);
            }
        }
#pragma unroll
        for (int b = 0; b < NB; b++) {
            float s0 = hadd2(aC0[b]); s0 += __shfl_xor_sync(0xffffffffu, s0, 16);
            float s1 = hadd2(aC1[b]); s1 += __shfl_xor_sync(0xffffffffu, s1, 16);
            float s2 = hadd2(aC2[b]); s2 += __shfl_xor_sync(0xffffffffu, s2, 16);
            float s3 = hadd2(aC3[b]); s3 += __shfl_xor_sync(0xffffffffu, s3, 16);
            g1b_s[b * NGATE + rX] = half ? s2 : s0;
            g1b_s[b * NGATE + rY] = half ? s3 : s1;
        }
    }
    __syncthreads();
    {   // act1(511)
        float p0 = g1a_s[gi1]       + g1b_s[gi1];
        float p1 = g1a_s[gi1 + 64]  + g1b_s[gi1 + 64];
        float p2 = g1a_s[gi1 + 128] + g1b_s[gi1 + 128];
        float p3 = g1a_s[gi1 + 192] + g1b_s[gi1 + 192];
        float i1 = sig_apx(p0), f1 = sig_apx(p1), g1v = tanh_apx(p2), o1 = sig_apx(p3);
        c1_1 = f1 * c1_1 + i1 * g1v;
        h1_s[hsto1] = o1 * tanh_apx(c1_1);
        if (tid < 128) {
            float e0 = g1a_s[gi2]       + g1b_s[gi2];
            float e1 = g1a_s[gi2 + 64]  + g1b_s[gi2 + 64];
            float e2 = g1a_s[gi2 + 128] + g1b_s[gi2 + 128];
            float e3 = g1a_s[gi2 + 192] + g1b_s[gi2 + 192];
            float i3 = sig_apx(e0), f3 = sig_apx(e1), g3v = tanh_apx(e2), o3 = sig_apx(e3);
            c1_2 = f3 * c1_2 + i3 * g3v;
            h1_s[hsto2] = o3 * tanh_apx(c1_2);
        }
    }
    __syncthreads();

    // ---- output FC ----
    if (tid < 16) {
        int b = tid & 7;
        const float* hp = (tid < 8) ? h0_s : h1_s;
        float s = b_fc[0];
#pragma unroll
        for (int uu = 0; uu < 64; uu++)
            s = fmaf(hp[b * HSTRIDE + uu + ((uu >> 5) << 2)], wfc_s[uu], s);
        out[(tid < 8 ? 0 : B_TOTAL) + bbase + b] = s;
    }
}

extern "C" void kernel_launch(void* const* d_in, const int* in_sizes, int n_in,
                              void* d_out, int out_size) {
    const float* x     = (const float*)d_in[0];
    const float* W_ih0 = (const float*)d_in[1];
    const float* W_hh0 = (const float*)d_in[2];
    const float* b_ih0 = (const float*)d_in[3];
    const float* b_hh0 = (const float*)d_in[4];
    const float* W_ih1 = (const float*)d_in[5];
    const float* W_hh1 = (const float*)d_in[6];
    const float* b_ih1 = (const float*)d_in[7];
    const float* b_hh1 = (const float*)d_in[8];
    const float* W_fc  = (const float*)d_in[9];
    const float* b_fc  = (const float*)d_in[10];
    float* out = (float*)d_out;

    cudaFuncSetAttribute(lstm2_kernel,
                         cudaFuncAttributeMaxDynamicSharedMemorySize, SMEM_BYTES);
    lstm2_kernel<<<NCTA, NTHREADS, SMEM_BYTES>>>(
        x, W_ih0, W_hh0, b_ih0, b_hh0,
        W_ih1, W_hh1, b_ih1, b_hh1, W_fc, b_fc, out);
}

// round 7
// speedup vs baseline: 7.4812x; 1.0998x over previous
#include <cuda_runtime.h>

#define B_TOTAL   1024
#define T_STEPS   512
#define NGATE     256
#define NB        8
#define NCTA      128
#define NTHREADS  384
#define HSTRIDE   68

typedef unsigned long long u64;

__device__ __forceinline__ u64 ffma2(u64 a, u64 b, u64 c) {
    u64 d;
    asm("fma.rn.f32x2 %0, %1, %2, %3;" : "=l"(d) : "l"(a), "l"(b), "l"(c));
    return d;
}
__device__ __forceinline__ float hadd2(u64 v) {
    float lo, hi;
    asm("mov.b64 {%0, %1}, %2;" : "=f"(lo), "=f"(hi) : "l"(v));
    return lo + hi;
}
__device__ __forceinline__ float tanh_apx(float x) {
    float y;
    asm("tanh.approx.f32 %0, %1;" : "=f"(y) : "f"(x));
    return y;
}
__device__ __forceinline__ float sig_apx(float x) {
    return fmaf(0.5f, tanh_apx(0.5f * x), 0.5f);
}

// SMEM (bytes):
//  wq   [0, 196608): quads. A=whh0 [0,4096), B=wih1 [4096,8192), C=whh1 [8192,12288)
//       A/B sublayout: [rowhi][kc][half][row&127]   (2048-quad blocks)  <-- conflict-free
//       C   sublayout: [row>>6][kc][half][row&63]   (1024-quad blocks)  <-- conflict-free
//  g0   [196608): f32 [8 b][256 g]
//  g1a  [204800): f32 [8 b][256 g]   (alpha partial, includes b1)
//  g1b  [212992): f32 [8 b][256 g]   (beta partial)
//  h0   [221184): f32 [8 b][68]      half0 @ +0, half1 @ +36 floats
//  h1   [223360)
//  wfc  [225536): f32 [64]
#define SM_W      0
#define SM_G0     196608
#define SM_G1A    204800
#define SM_G1B    212992
#define SM_H0     221184
#define SM_H1     223360
#define SM_WFC    225536
#define SMEM_BYTES 225792

__global__ void __launch_bounds__(NTHREADS, 1)
lstm2_kernel(const float* __restrict__ x,
             const float* __restrict__ W_ih0, const float* __restrict__ W_hh0,
             const float* __restrict__ b_ih0, const float* __restrict__ b_hh0,
             const float* __restrict__ W_ih1, const float* __restrict__ W_hh1,
             const float* __restrict__ b_ih1, const float* __restrict__ b_hh1,
             const float* __restrict__ W_fc,  const float* __restrict__ b_fc,
             float* __restrict__ out)
{
    extern __shared__ char smem[];
    ulonglong2* wq = (ulonglong2*)(smem + SM_W);
    float* g0_s  = (float*)(smem + SM_G0);
    float* g1a_s = (float*)(smem + SM_G1A);
    float* g1b_s = (float*)(smem + SM_G1B);
    float* h0_s  = (float*)(smem + SM_H0);
    float* h1_s  = (float*)(smem + SM_H1);
    float* wfc_s = (float*)(smem + SM_WFC);

    const int tid   = threadIdx.x;
    const int bbase = blockIdx.x * NB;
    const int lane  = tid & 31;
    const int half  = lane >> 4;        // k-half within warp
    const int hofs  = half * 36;        // h chunk float offset
    const int wid   = tid >> 5;

    // ---- upload weights into conflict-free role-specific quad layouts ----
    for (int idx = tid; idx < 4096; idx += NTHREADS) {
        int row = idx >> 4, q = idx & 15;
        int hh = q >> 3, kc = q & 7;
        int dA = (row >> 7) * 2048 + kc * 256 + hh * 128 + (row & 127);
        wq[dA]        = ((const ulonglong2*)W_hh0)[idx];
        wq[4096 + dA] = ((const ulonglong2*)W_ih1)[idx];
        int dC = 8192 + (row >> 6) * 1024 + kc * 128 + hh * 64 + (row & 63);
        wq[dC] = ((const ulonglong2*)W_hh1)[idx];
    }
    if (tid < 64) wfc_s[tid] = W_fc[tid];
    for (int i = tid; i < NB * HSTRIDE; i += NTHREADS) { h0_s[i] = 0.0f; h1_s[i] = 0.0f; }

    // ---- role constants ----
    const bool isA = (tid < 256);
    // alpha: warps 0-7, slot sl in [0,128), rows {sl, sl+128}
    const int sl    = (wid & 7) * 16 + (lane & 15);
    const int wofsA = half * 128 + sl;          // conflict-free weight index
    const int myrow = sl + half * 128;          // row this lane stores
    // beta: warps 8-11, slot sb in [0,64), rows {sb, sb+64, sb+128, sb+192}
    const int sb    = (wid - 8) * 16 + (lane & 15);
    const int wofsC = half * 64 + sb;
    const int rX    = sb + 64 * (half * 2);     // beta store rows
    const int rY    = rX + 64;

    float b0v = 0.0f, b1v = 0.0f;
    if (isA) {
        b0v = b_ih0[myrow] + b_hh0[myrow];
        b1v = b_ih1[myrow] + b_hh1[myrow];
    }

    // ---- act ownership: cell1 = tid; cell2 = 384 + tid (tid<128) ----
    const int u   = tid & 63;
    const int b1c = tid >> 6;                   // 0..5
    const int b2c = b1c + 6;                    // 6..7 for tid<128
    const int gi1 = b1c * NGATE + u;
    const int gi2 = b2c * NGATE + u;
    const int pad = (u >> 5) << 2;
    const int hsto1 = b1c * HSTRIDE + u + pad;
    const int hsto2 = b2c * HSTRIDE + u + pad;
    const float* xrow1 = x + (size_t)(bbase + b1c) * T_STEPS;
    const float* xrow2 = x + (size_t)(bbase + b2c) * T_STEPS;
    const float wxi = W_ih0[u];
    const float wxf = W_ih0[64 + u];
    const float wxg = W_ih0[128 + u];
    const float wxo = W_ih0[192 + u];
    float c0_1 = 0.0f, c1_1 = 0.0f, c0_2 = 0.0f, c1_2 = 0.0f;

    // ---- prologue: g0(0) = b0 ----
    if (isA) {
#pragma unroll
        for (int b = 0; b < NB; b++) g0_s[b * NGATE + myrow] = b0v;
    }
    __syncthreads();
    {   // act0(0)
        float xv = __ldg(xrow1);
        float q0 = fmaf(wxi, xv, g0_s[gi1]);
        float q1 = fmaf(wxf, xv, g0_s[gi1 + 64]);
        float q2 = fmaf(wxg, xv, g0_s[gi1 + 128]);
        float q3 = fmaf(wxo, xv, g0_s[gi1 + 192]);
        float i0 = sig_apx(q0), f0 = sig_apx(q1), g0v = tanh_apx(q2), o0 = sig_apx(q3);
        c0_1 = f0 * c0_1 + i0 * g0v;
        h0_s[hsto1] = o0 * tanh_apx(c0_1);
        if (tid < 128) {
            float xw = __ldg(xrow2);
            float r0 = fmaf(wxi, xw, g0_s[gi2]);
            float r1 = fmaf(wxf, xw, g0_s[gi2 + 64]);
            float r2 = fmaf(wxg, xw, g0_s[gi2 + 128]);
            float r3 = fmaf(wxo, xw, g0_s[gi2 + 192]);
            float i2 = sig_apx(r0), f2 = sig_apx(r1), g2v = tanh_apx(r2), o2 = sig_apx(r3);
            c0_2 = f2 * c0_2 + i2 * g2v;
            h0_s[hsto2] = o2 * tanh_apx(c0_2);
        }
    }
    __syncthreads();

    // ======== main loop ========
    for (int t = 0; t < T_STEPS - 1; t++) {
        if (isA) {
            u64 aA0[NB], aA1[NB], aB0[NB], aB1[NB];
#pragma unroll
            for (int b = 0; b < NB; b++) { aA0[b]=0ull; aA1[b]=0ull; aB0[b]=0ull; aB1[b]=0ull; }
#pragma unroll
            for (int kc = 0; kc < 8; kc++) {
                ulonglong2 wa0 = wq[       kc * 256 + wofsA];
                ulonglong2 wa1 = wq[2048 + kc * 256 + wofsA];
                ulonglong2 wb0 = wq[4096 + kc * 256 + wofsA];
                ulonglong2 wb1 = wq[6144 + kc * 256 + wofsA];
#pragma unroll
                for (int b = 0; b < NB; b++) {
                    ulonglong2 h2 = *(const ulonglong2*)(h0_s + b * HSTRIDE + hofs + kc * 4);
                    aA0[b] = ffma2(wa0.x, h2.x, aA0[b]); aA0[b] = ffma2(wa0.y, h2.y, aA0[b]);
                    aA1[b] = ffma2(wa1.x, h2.x, aA1[b]); aA1[b] = ffma2(wa1.y, h2.y, aA1[b]);
                    aB0[b] = ffma2(wb0.x, h2.x, aB0[b]); aB0[b] = ffma2(wb0.y, h2.y, aB0[b]);
                    aB1[b] = ffma2(wb1.x, h2.x, aB1[b]); aB1[b] = ffma2(wb1.y, h2.y, aB1[b]);
                }
            }
#pragma unroll
            for (int b = 0; b < NB; b++) {
                float sA0 = hadd2(aA0[b]); sA0 += __shfl_xor_sync(0xffffffffu, sA0, 16);
                float sA1 = hadd2(aA1[b]); sA1 += __shfl_xor_sync(0xffffffffu, sA1, 16);
                float sB0 = hadd2(aB0[b]); sB0 += __shfl_xor_sync(0xffffffffu, sB0, 16);
                float sB1 = hadd2(aB1[b]); sB1 += __shfl_xor_sync(0xffffffffu, sB1, 16);
                g0_s [b * NGATE + myrow] = (half ? sA1 : sA0) + b0v;
                g1a_s[b * NGATE + myrow] = (half ? sB1 : sB0) + b1v;
            }
        } else {
            u64 aC0[NB], aC1[NB], aC2[NB], aC3[NB];
#pragma unroll
            for (int b = 0; b < NB; b++) { aC0[b]=0ull; aC1[b]=0ull; aC2[b]=0ull; aC3[b]=0ull; }
#pragma unroll
            for (int kc = 0; kc < 8; kc++) {
                ulonglong2 wc0 = wq[8192        + kc * 128 + wofsC];
                ulonglong2 wc1 = wq[8192 + 1024 + kc * 128 + wofsC];
                ulonglong2 wc2 = wq[8192 + 2048 + kc * 128 + wofsC];
                ulonglong2 wc3 = wq[8192 + 3072 + kc * 128 + wofsC];
#pragma unroll
                for (int b = 0; b < NB; b++) {
                    ulonglong2 h2 = *(const ulonglong2*)(h1_s + b * HSTRIDE + hofs + kc * 4);
                    aC0[b] = ffma2(wc0.x, h2.x, aC0[b]); aC0[b] = ffma2(wc0.y, h2.y, aC0[b]);
                    aC1[b] = ffma2(wc1.x, h2.x, aC1[b]); aC1[b] = ffma2(wc1.y, h2.y, aC1[b]);
                    aC2[b] = ffma2(wc2.x, h2.x, aC2[b]); aC2[b] = ffma2(wc2.y, h2.y, aC2[b]);
                    aC3[b] = ffma2(wc3.x, h2.x, aC3[b]); aC3[b] = ffma2(wc3.y, h2.y, aC3[b]);
                }
            }
#pragma unroll
            for (int b = 0; b < NB; b++) {
                float s0 = hadd2(aC0[b]); s0 += __shfl_xor_sync(0xffffffffu, s0, 16);
                float s1 = hadd2(aC1[b]); s1 += __shfl_xor_sync(0xffffffffu, s1, 16);
                float s2 = hadd2(aC2[b]); s2 += __shfl_xor_sync(0xffffffffu, s2, 16);
                float s3 = hadd2(aC3[b]); s3 += __shfl_xor_sync(0xffffffffu, s3, 16);
                g1b_s[b * NGATE + rX] = half ? s2 : s0;
                g1b_s[b * NGATE + rY] = half ? s3 : s1;
            }
        }
        __syncthreads();   // A -> B

        // ---- act1(t), act0(t+1) ----
        {
            float xv = __ldg(xrow1 + t + 1);
            float p0 = g1a_s[gi1]       + g1b_s[gi1];
            float p1 = g1a_s[gi1 + 64]  + g1b_s[gi1 + 64];
            float p2 = g1a_s[gi1 + 128] + g1b_s[gi1 + 128];
            float p3 = g1a_s[gi1 + 192] + g1b_s[gi1 + 192];
            float q0 = fmaf(wxi, xv, g0_s[gi1]);
            float q1 = fmaf(wxf, xv, g0_s[gi1 + 64]);
            float q2 = fmaf(wxg, xv, g0_s[gi1 + 128]);
            float q3 = fmaf(wxo, xv, g0_s[gi1 + 192]);
            float i1 = sig_apx(p0), f1 = sig_apx(p1), g1v = tanh_apx(p2), o1 = sig_apx(p3);
            float i0 = sig_apx(q0), f0 = sig_apx(q1), g0v = tanh_apx(q2), o0 = sig_apx(q3);
            c1_1 = f1 * c1_1 + i1 * g1v;
            c0_1 = f0 * c0_1 + i0 * g0v;
            h1_s[hsto1] = o1 * tanh_apx(c1_1);
            h0_s[hsto1] = o0 * tanh_apx(c0_1);

            if (tid < 128) {
                float xw = __ldg(xrow2 + t + 1);
                float e0 = g1a_s[gi2]       + g1b_s[gi2];
                float e1 = g1a_s[gi2 + 64]  + g1b_s[gi2 + 64];
                float e2 = g1a_s[gi2 + 128] + g1b_s[gi2 + 128];
                float e3 = g1a_s[gi2 + 192] + g1b_s[gi2 + 192];
                float r0 = fmaf(wxi, xw, g0_s[gi2]);
                float r1 = fmaf(wxf, xw, g0_s[gi2 + 64]);
                float r2 = fmaf(wxg, xw, g0_s[gi2 + 128]);
                float r3 = fmaf(wxo, xw, g0_s[gi2 + 192]);
                float i3 = sig_apx(e0), f3 = sig_apx(e1), g3v = tanh_apx(e2), o3 = sig_apx(e3);
                float i2 = sig_apx(r0), f2 = sig_apx(r1), g2v = tanh_apx(r2), o2 = sig_apx(r3);
                c1_2 = f3 * c1_2 + i3 * g3v;
                c0_2 = f2 * c0_2 + i2 * g2v;
                h1_s[hsto2] = o3 * tanh_apx(c1_2);
                h0_s[hsto2] = o2 * tanh_apx(c0_2);
            }
        }
        __syncthreads();   // B -> A
    }

    // ======== epilogue: mv1(511) + act1(511) ========
    if (isA) {
        u64 aB0[NB], aB1[NB];
#pragma unroll
        for (int b = 0; b < NB; b++) { aB0[b] = 0ull; aB1[b] = 0ull; }
#pragma unroll
        for (int kc = 0; kc < 8; kc++) {
            ulonglong2 wb0 = wq[4096 + kc * 256 + wofsA];
            ulonglong2 wb1 = wq[6144 + kc * 256 + wofsA];
#pragma unroll
            for (int b = 0; b < NB; b++) {
                ulonglong2 h2 = *(const ulonglong2*)(h0_s + b * HSTRIDE + hofs + kc * 4);
                aB0[b] = ffma2(wb0.x, h2.x, aB0[b]); aB0[b] = ffma2(wb0.y, h2.y, aB0[b]);
                aB1[b] = ffma2(wb1.x, h2.x, aB1[b]); aB1[b] = ffma2(wb1.y, h2.y, aB1[b]);
            }
        }
#pragma unroll
        for (int b = 0; b < NB; b++) {
            float sB0 = hadd2(aB0[b]); sB0 += __shfl_xor_sync(0xffffffffu, sB0, 16);
            float sB1 = hadd2(aB1[b]); sB1 += __shfl_xor_sync(0xffffffffu, sB1, 16);
            g1a_s[b * NGATE + myrow] = (half ? sB1 : sB0) + b1v;
        }
    } else {
        u64 aC0[NB], aC1[NB], aC2[NB], aC3[NB];
#pragma unroll
        for (int b = 0; b < NB; b++) { aC0[b]=0ull; aC1[b]=0ull; aC2[b]=0ull; aC3[b]=0ull; }
#pragma unroll
        for (int kc = 0; kc < 8; kc++) {
            ulonglong2 wc0 = wq[8192        + kc * 128 + wofsC];
            ulonglong2 wc1 = wq[8192 + 1024 + kc * 128 + wofsC];
            ulonglong2 wc2 = wq[8192 + 2048 + kc * 128 + wofsC];
            ulonglong2 wc3 = wq[8192 + 3072 + kc * 128 + wofsC];
#pragma unroll
            for (int b = 0; b < NB; b++) {
                ulonglong2 h2 = *(const ulonglong2*)(h1_s + b * HSTRIDE + hofs + kc * 4);
                aC0[b] = ffma2(wc0.x, h2.x, aC0[b]); aC0[b] = ffma2(wc0.y, h2.y, aC0[b]);
                aC1[b] = ffma2(wc1.x, h2.x, aC1[b]); aC1[b] = ffma2(wc1.y, h2.y, aC1[b]);
                aC2[b] = ffma2(wc2.x, h2.x, aC2[b]); aC2[b] = ffma2(wc2.y, h2.y, aC2[b]);
                aC3[b] = ffma2(wc3.x, h2.x, aC3[b]); aC3[b] = ffma2(wc3.y, h2.y, aC3[b]);
            }
        }
#pragma unroll
        for (int b = 0; b < NB; b++) {
            float s0 = hadd2(aC0[b]); s0 += __shfl_xor_sync(0xffffffffu, s0, 16);
            float s1 = hadd2(aC1[b]); s1 += __shfl_xor_sync(0xffffffffu, s1, 16);
            float s2 = hadd2(aC2[b]); s2 += __shfl_xor_sync(0xffffffffu, s2, 16);
            float s3 = hadd2(aC3[b]); s3 += __shfl_xor_sync(0xffffffffu, s3, 16);
            g1b_s[b * NGATE + rX] = half ? s2 : s0;
            g1b_s[b * NGATE + rY] = half ? s3 : s1;
        }
    }
    __syncthreads();
    {   // act1(511)
        float p0 = g1a_s[gi1]       + g1b_s[gi1];
        float p1 = g1a_s[gi1 + 64]  + g1b_s[gi1 + 64];
        float p2 = g1a_s[gi1 + 128] + g1b_s[gi1 + 128];
        float p3 = g1a_s[gi1 + 192] + g1b_s[gi1 + 192];
        float i1 = sig_apx(p0), f1 = sig_apx(p1), g1v = tanh_apx(p2), o1 = sig_apx(p3);
        c1_1 = f1 * c1_1 + i1 * g1v;
        h1_s[hsto1] = o1 * tanh_apx(c1_1);
        if (tid < 128) {
            float e0 = g1a_s[gi2]       + g1b_s[gi2];
            float e1 = g1a_s[gi2 + 64]  + g1b_s[gi2 + 64];
            float e2 = g1a_s[gi2 + 128] + g1b_s[gi2 + 128];
            float e3 = g1a_s[gi2 + 192] + g1b_s[gi2 + 192];
            float i3 = sig_apx(e0), f3 = sig_apx(e1), g3v = tanh_apx(e2), o3 = sig_apx(e3);
            c1_2 = f3 * c1_2 + i3 * g3v;
            h1_s[hsto2] = o3 * tanh_apx(c1_2);
        }
    }
    __syncthreads();

    // ---- output FC ----
    if (tid < 16) {
        int b = tid & 7;
        const float* hp = (tid < 8) ? h0_s : h1_s;
        float s = b_fc[0];
#pragma unroll
        for (int uu = 0; uu < 64; uu++)
            s = fmaf(hp[b * HSTRIDE + uu + ((uu >> 5) << 2)], wfc_s[uu], s);
        out[(tid < 8 ? 0 : B_TOTAL) + bbase + b] = s;
    }
}

extern "C" void kernel_launch(void* const* d_in, const int* in_sizes, int n_in,
                              void* d_out, int out_size) {
    const float* x     = (const float*)d_in[0];
    const float* W_ih0 = (const float*)d_in[1];
    const float* W_hh0 = (const float*)d_in[2];
    const float* b_ih0 = (const float*)d_in[3];
    const float* b_hh0 = (const float*)d_in[4];
    const float* W_ih1 = (const float*)d_in[5];
    const float* W_hh1 = (const float*)d_in[6];
    const float* b_ih1 = (const float*)d_in[7];
    const float* b_hh1 = (const float*)d_in[8];
    const float* W_fc  = (const float*)d_in[9];
    const float* b_fc  = (const float*)d_in[10];
    float* out = (float*)d_out;

    cudaFuncSetAttribute(lstm2_kernel,
                         cudaFuncAttributeMaxDynamicSharedMemorySize, SMEM_BYTES);
    lstm2_kernel<<<NCTA, NTHREADS, SMEM_BYTES>>>(
        x, W_ih0, W_hh0, b_ih0, b_hh0,
        W_ih1, W_hh1, b_ih1, b_hh1, W_fc, b_fc, out);
}

// round 8
// speedup vs baseline: 7.6475x; 1.0222x over previous
#include <cuda_runtime.h>

#define B_TOTAL   1024
#define T_STEPS   512
#define NGATE     256
#define NB        8
#define NCTA      128
#define NTHREADS  384
#define HSTRIDE   68

typedef unsigned long long u64;

__device__ __forceinline__ u64 ffma2(u64 a, u64 b, u64 c) {
    u64 d;
    asm("fma.rn.f32x2 %0, %1, %2, %3;" : "=l"(d) : "l"(a), "l"(b), "l"(c));
    return d;
}
__device__ __forceinline__ float hadd2(u64 v) {
    float lo, hi;
    asm("mov.b64 {%0, %1}, %2;" : "=f"(lo), "=f"(hi) : "l"(v));
    return lo + hi;
}
__device__ __forceinline__ float tanh_apx(float x) {
    float y;
    asm("tanh.approx.f32 %0, %1;" : "=f"(y) : "f"(x));
    return y;
}
__device__ __forceinline__ float sig_apx(float x) {
    return fmaf(0.5f, tanh_apx(0.5f * x), 0.5f);
}

// SMEM (bytes):
//  wq   [0, 196608): quads. A=whh0 [0,4096), B=wih1 [4096,8192), C=whh1 [8192,12288)
//       A/B sublayout: [rowhi][kc][half][row&127]   (2048-quad blocks)  conflict-free
//       C   sublayout: [row>>6][kc][half][row&63]   (1024-quad blocks)  conflict-free
//  g0   [196608): f32 [8 b][256 g]
//  g1a  [204800): f32 [8 b][256 g]   (alpha partial, includes b1)
//  g1b  [212992): f32 [8 b][256 g]   (beta partial)
//  h0   [221184): f32 [8 b][68]      half0 @ +0, half1 @ +36 floats
//  h1   [223360)
//  wfc  [225536): f32 [64]
#define SM_W      0
#define SM_G0     196608
#define SM_G1A    204800
#define SM_G1B    212992
#define SM_H0     221184
#define SM_H1     223360
#define SM_WFC    225536
#define SMEM_BYTES 225792

__global__ void __launch_bounds__(NTHREADS, 1)
lstm2_kernel(const float* __restrict__ x,
             const float* __restrict__ W_ih0, const float* __restrict__ W_hh0,
             const float* __restrict__ b_ih0, const float* __restrict__ b_hh0,
             const float* __restrict__ W_ih1, const float* __restrict__ W_hh1,
             const float* __restrict__ b_ih1, const float* __restrict__ b_hh1,
             const float* __restrict__ W_fc,  const float* __restrict__ b_fc,
             float* __restrict__ out)
{
    extern __shared__ char smem[];
    ulonglong2* wq = (ulonglong2*)(smem + SM_W);
    float* g0_s  = (float*)(smem + SM_G0);
    float* g1a_s = (float*)(smem + SM_G1A);
    float* g1b_s = (float*)(smem + SM_G1B);
    float* h0_s  = (float*)(smem + SM_H0);
    float* h1_s  = (float*)(smem + SM_H1);
    float* wfc_s = (float*)(smem + SM_WFC);

    const int tid   = threadIdx.x;
    const int bbase = blockIdx.x * NB;
    const int lane  = tid & 31;
    const int half  = lane >> 4;        // k-half within warp
    const int hofs  = half * 36;        // h chunk float offset
    const int wid   = tid >> 5;

    // ---- upload weights into conflict-free role-specific quad layouts ----
    for (int idx = tid; idx < 4096; idx += NTHREADS) {
        int row = idx >> 4, q = idx & 15;
        int hh = q >> 3, kc = q & 7;
        int dA = (row >> 7) * 2048 + kc * 256 + hh * 128 + (row & 127);
        wq[dA]        = ((const ulonglong2*)W_hh0)[idx];
        wq[4096 + dA] = ((const ulonglong2*)W_ih1)[idx];
        int dC = 8192 + (row >> 6) * 1024 + kc * 128 + hh * 64 + (row & 63);
        wq[dC] = ((const ulonglong2*)W_hh1)[idx];
    }
    if (tid < 64) wfc_s[tid] = W_fc[tid];
    for (int i = tid; i < NB * HSTRIDE; i += NTHREADS) { h0_s[i] = 0.0f; h1_s[i] = 0.0f; }

    // ---- matvec role constants ----
    const bool isA = (tid < 256);
    const int sl    = (wid & 7) * 16 + (lane & 15);
    const int wofsA = half * 128 + sl;
    const int myrow = sl + half * 128;
    const int sb    = (wid - 8) * 16 + (lane & 15);
    const int wofsC = half * 64 + sb;
    const int rX    = sb + 64 * (half * 2);
    const int rY    = rX + 64;

    float b0v = 0.0f, b1v = 0.0f;
    if (isA) {
        b0v = b_ih0[myrow] + b_hh0[myrow];
        b1v = b_ih1[myrow] + b_hh1[myrow];
    }

    // ---- act ownership: unit j = tid + 384*j ; tid<256 -> 3 units, else 2 ----
    // unit0: always layer0. unit1: layer0 if tid<128 else layer1. unit2 (tid<256): layer1.
    const int u    = tid & 63;                 // same u for all units (384*j % 64 == 0)
    const int b0u  = (tid >> 6) & 7;
    const int b1u  = ((tid + 384) >> 6) & 7;
    const int b2u  = ((tid + 768) >> 6) & 7;
    const bool u1L0  = (tid < 128);
    const bool hasU2 = (tid < 256);
    const int pad  = (u >> 5) << 2;
    const int hs0  = b0u * HSTRIDE + u + pad;
    const int hs1  = b1u * HSTRIDE + u + pad;
    const int hs2  = b2u * HSTRIDE + u + pad;
    const int gi0  = b0u * NGATE + u;
    const int gi1u = b1u * NGATE + u;
    const int gi2u = b2u * NGATE + u;
    const float* xr0 = x + (size_t)(bbase + b0u) * T_STEPS;
    const float* xr1 = x + (size_t)(bbase + b1u) * T_STEPS;   // only if u1L0
    const float wxi = W_ih0[u];
    const float wxf = W_ih0[64 + u];
    const float wxg = W_ih0[128 + u];
    const float wxo = W_ih0[192 + u];
    float cu0 = 0.0f, cu1 = 0.0f, cu2 = 0.0f;

    auto actL0 = [&](int gi, int hs, float& c, float xv) {
        float q0 = fmaf(wxi, xv, g0_s[gi]);
        float q1 = fmaf(wxf, xv, g0_s[gi + 64]);
        float q2 = fmaf(wxg, xv, g0_s[gi + 128]);
        float q3 = fmaf(wxo, xv, g0_s[gi + 192]);
        float ii = sig_apx(q0), ff = sig_apx(q1), gv = tanh_apx(q2), oo = sig_apx(q3);
        c = ff * c + ii * gv;
        h0_s[hs] = oo * tanh_apx(c);
    };
    auto actL1 = [&](int gi, int hs, float& c) {
        float p0 = g1a_s[gi]       + g1b_s[gi];
        float p1 = g1a_s[gi + 64]  + g1b_s[gi + 64];
        float p2 = g1a_s[gi + 128] + g1b_s[gi + 128];
        float p3 = g1a_s[gi + 192] + g1b_s[gi + 192];
        float ii = sig_apx(p0), ff = sig_apx(p1), gv = tanh_apx(p2), oo = sig_apx(p3);
        c = ff * c + ii * gv;
        h1_s[hs] = oo * tanh_apx(c);
    };

    __syncthreads();

    // ---- prologue: g0(0) = b0, then act0(0) over all layer-0 cells ----
    if (isA) {
#pragma unroll
        for (int b = 0; b < NB; b++) g0_s[b * NGATE + myrow] = b0v;
    }
    __syncthreads();
    actL0(gi0, hs0, cu0, __ldg(xr0));
    if (u1L0) actL0(gi1u, hs1, cu1, __ldg(xr1));
    __syncthreads();

    // ======== main loop ========
    for (int t = 0; t < T_STEPS - 1; t++) {
        if (isA) {
            u64 aA0[NB], aA1[NB], aB0[NB], aB1[NB];
#pragma unroll
            for (int b = 0; b < NB; b++) { aA0[b]=0ull; aA1[b]=0ull; aB0[b]=0ull; aB1[b]=0ull; }
#pragma unroll
            for (int kc = 0; kc < 8; kc++) {
                ulonglong2 wa0 = wq[       kc * 256 + wofsA];
                ulonglong2 wa1 = wq[2048 + kc * 256 + wofsA];
                ulonglong2 wb0 = wq[4096 + kc * 256 + wofsA];
                ulonglong2 wb1 = wq[6144 + kc * 256 + wofsA];
#pragma unroll
                for (int b = 0; b < NB; b++) {
                    ulonglong2 h2 = *(const ulonglong2*)(h0_s + b * HSTRIDE + hofs + kc * 4);
                    aA0[b] = ffma2(wa0.x, h2.x, aA0[b]); aA0[b] = ffma2(wa0.y, h2.y, aA0[b]);
                    aA1[b] = ffma2(wa1.x, h2.x, aA1[b]); aA1[b] = ffma2(wa1.y, h2.y, aA1[b]);
                    aB0[b] = ffma2(wb0.x, h2.x, aB0[b]); aB0[b] = ffma2(wb0.y, h2.y, aB0[b]);
                    aB1[b] = ffma2(wb1.x, h2.x, aB1[b]); aB1[b] = ffma2(wb1.y, h2.y, aB1[b]);
                }
            }
#pragma unroll
            for (int b = 0; b < NB; b++) {
                float sA0 = hadd2(aA0[b]); sA0 += __shfl_xor_sync(0xffffffffu, sA0, 16);
                float sA1 = hadd2(aA1[b]); sA1 += __shfl_xor_sync(0xffffffffu, sA1, 16);
                float sB0 = hadd2(aB0[b]); sB0 += __shfl_xor_sync(0xffffffffu, sB0, 16);
                float sB1 = hadd2(aB1[b]); sB1 += __shfl_xor_sync(0xffffffffu, sB1, 16);
                g0_s [b * NGATE + myrow] = (half ? sA1 : sA0) + b0v;
                g1a_s[b * NGATE + myrow] = (half ? sB1 : sB0) + b1v;
            }
        } else {
            u64 aC0[NB], aC1[NB], aC2[NB], aC3[NB];
#pragma unroll
            for (int b = 0; b < NB; b++) { aC0[b]=0ull; aC1[b]=0ull; aC2[b]=0ull; aC3[b]=0ull; }
#pragma unroll
            for (int kc = 0; kc < 8; kc++) {
                ulonglong2 wc0 = wq[8192        + kc * 128 + wofsC];
                ulonglong2 wc1 = wq[8192 + 1024 + kc * 128 + wofsC];
                ulonglong2 wc2 = wq[8192 + 2048 + kc * 128 + wofsC];
                ulonglong2 wc3 = wq[8192 + 3072 + kc * 128 + wofsC];
#pragma unroll
                for (int b = 0; b < NB; b++) {
                    ulonglong2 h2 = *(const ulonglong2*)(h1_s + b * HSTRIDE + hofs + kc * 4);
                    aC0[b] = ffma2(wc0.x, h2.x, aC0[b]); aC0[b] = ffma2(wc0.y, h2.y, aC0[b]);
                    aC1[b] = ffma2(wc1.x, h2.x, aC1[b]); aC1[b] = ffma2(wc1.y, h2.y, aC1[b]);
                    aC2[b] = ffma2(wc2.x, h2.x, aC2[b]); aC2[b] = ffma2(wc2.y, h2.y, aC2[b]);
                    aC3[b] = ffma2(wc3.x, h2.x, aC3[b]); aC3[b] = ffma2(wc3.y, h2.y, aC3[b]);
                }
            }
#pragma unroll
            for (int b = 0; b < NB; b++) {
                float s0 = hadd2(aC0[b]); s0 += __shfl_xor_sync(0xffffffffu, s0, 16);
                float s1 = hadd2(aC1[b]); s1 += __shfl_xor_sync(0xffffffffu, s1, 16);
                float s2 = hadd2(aC2[b]); s2 += __shfl_xor_sync(0xffffffffu, s2, 16);
                float s3 = hadd2(aC3[b]); s3 += __shfl_xor_sync(0xffffffffu, s3, 16);
                g1b_s[b * NGATE + rX] = half ? s2 : s0;
                g1b_s[b * NGATE + rY] = half ? s3 : s1;
            }
        }
        __syncthreads();   // A -> B

        // ---- balanced act: act1(t) + act0(t+1), <=3 units/thread ----
        {
            float xv0 = __ldg(xr0 + t + 1);
            if (u1L0) {                       // tid < 128: L0, L0, L1
                float xv1 = __ldg(xr1 + t + 1);
                actL0(gi0,  hs0, cu0, xv0);
                actL0(gi1u, hs1, cu1, xv1);
                actL1(gi2u, hs2, cu2);
            } else if (hasU2) {               // 128..255: L0, L1, L1
                actL0(gi0,  hs0, cu0, xv0);
                actL1(gi1u, hs1, cu1);
                actL1(gi2u, hs2, cu2);
            } else {                          // 256..383: L0, L1
                actL0(gi0,  hs0, cu0, xv0);
                actL1(gi1u, hs1, cu1);
            }
        }
        __syncthreads();   // B -> A
    }

    // ======== epilogue: mv1(511) + act1(511) ========
    if (isA) {
        u64 aB0[NB], aB1[NB];
#pragma unroll
        for (int b = 0; b < NB; b++) { aB0[b] = 0ull; aB1[b] = 0ull; }
#pragma unroll
        for (int kc = 0; kc < 8; kc++) {
            ulonglong2 wb0 = wq[4096 + kc * 256 + wofsA];
            ulonglong2 wb1 = wq[6144 + kc * 256 + wofsA];
#pragma unroll
            for (int b = 0; b < NB; b++) {
                ulonglong2 h2 = *(const ulonglong2*)(h0_s + b * HSTRIDE + hofs + kc * 4);
                aB0[b] = ffma2(wb0.x, h2.x, aB0[b]); aB0[b] = ffma2(wb0.y, h2.y, aB0[b]);
                aB1[b] = ffma2(wb1.x, h2.x, aB1[b]); aB1[b] = ffma2(wb1.y, h2.y, aB1[b]);
            }
        }
#pragma unroll
        for (int b = 0; b < NB; b++) {
            float sB0 = hadd2(aB0[b]); sB0 += __shfl_xor_sync(0xffffffffu, sB0, 16);
            float sB1 = hadd2(aB1[b]); sB1 += __shfl_xor_sync(0xffffffffu, sB1, 16);
            g1a_s[b * NGATE + myrow] = (half ? sB1 : sB0) + b1v;
        }
    } else {
        u64 aC0[NB], aC1[NB], aC2[NB], aC3[NB];
#pragma unroll
        for (int b = 0; b < NB; b++) { aC0[b]=0ull; aC1[b]=0ull; aC2[b]=0ull; aC3[b]=0ull; }
#pragma unroll
        for (int kc = 0; kc < 8; kc++) {
            ulonglong2 wc0 = wq[8192        + kc * 128 + wofsC];
            ulonglong2 wc1 = wq[8192 + 1024 + kc * 128 + wofsC];
            ulonglong2 wc2 = wq[8192 + 2048 + kc * 128 + wofsC];
            ulonglong2 wc3 = wq[8192 + 3072 + kc * 128 + wofsC];
#pragma unroll
            for (int b = 0; b < NB; b++) {
                ulonglong2 h2 = *(const ulonglong2*)(h1_s + b * HSTRIDE + hofs + kc * 4);
                aC0[b] = ffma2(wc0.x, h2.x, aC0[b]); aC0[b] = ffma2(wc0.y, h2.y, aC0[b]);
                aC1[b] = ffma2(wc1.x, h2.x, aC1[b]); aC1[b] = ffma2(wc1.y, h2.y, aC1[b]);
                aC2[b] = ffma2(wc2.x, h2.x, aC2[b]); aC2[b] = ffma2(wc2.y, h2.y, aC2[b]);
                aC3[b] = ffma2(wc3.x, h2.x, aC3[b]); aC3[b] = ffma2(wc3.y, h2.y, aC3[b]);
            }
        }
#pragma unroll
        for (int b = 0; b < NB; b++) {
            float s0 = hadd2(aC0[b]); s0 += __shfl_xor_sync(0xffffffffu, s0, 16);
            float s1 = hadd2(aC1[b]); s1 += __shfl_xor_sync(0xffffffffu, s1, 16);
            float s2 = hadd2(aC2[b]); s2 += __shfl_xor_sync(0xffffffffu, s2, 16);
            float s3 = hadd2(aC3[b]); s3 += __shfl_xor_sync(0xffffffffu, s3, 16);
            g1b_s[b * NGATE + rX] = half ? s2 : s0;
            g1b_s[b * NGATE + rY] = half ? s3 : s1;
        }
    }
    __syncthreads();
    {   // act1(511): layer-1 units are unit1 (tid>=128) and unit2 (tid<256)
        if (!u1L0) actL1(gi1u, hs1, cu1);
        if (hasU2) actL1(gi2u, hs2, cu2);
    }
    __syncthreads();

    // ---- output FC ----
    if (tid < 16) {
        int b = tid & 7;
        const float* hp = (tid < 8) ? h0_s : h1_s;
        float s = b_fc[0];
#pragma unroll
        for (int uu = 0; uu < 64; uu++)
            s = fmaf(hp[b * HSTRIDE + uu + ((uu >> 5) << 2)], wfc_s[uu], s);
        out[(tid < 8 ? 0 : B_TOTAL) + bbase + b] = s;
    }
}

extern "C" void kernel_launch(void* const* d_in, const int* in_sizes, int n_in,
                              void* d_out, int out_size) {
    const float* x     = (const float*)d_in[0];
    const float* W_ih0 = (const float*)d_in[1];
    const float* W_hh0 = (const float*)d_in[2];
    const float* b_ih0 = (const float*)d_in[3];
    const float* b_hh0 = (const float*)d_in[4];
    const float* W_ih1 = (const float*)d_in[5];
    const float* W_hh1 = (const float*)d_in[6];
    const float* b_ih1 = (const float*)d_in[7];
    const float* b_hh1 = (const float*)d_in[8];
    const float* W_fc  = (const float*)d_in[9];
    const float* b_fc  = (const float*)d_in[10];
    float* out = (float*)d_out;

    cudaFuncSetAttribute(lstm2_kernel,
                         cudaFuncAttributeMaxDynamicSharedMemorySize, SMEM_BYTES);
    lstm2_kernel<<<NCTA, NTHREADS, SMEM_BYTES>>>(
        x, W_ih0, W_hh0, b_ih0, b_hh0,
        W_ih1, W_hh1, b_ih1, b_hh1, W_fc, b_fc, out);
}